// round 9
// baseline (speedup 1.0000x reference)
#include <cuda_runtime.h>
#include <cuda_fp16.h>
#include <math.h>
#include <stdint.h>

// Problem dims (fixed by the dataset)
#define BT  4096     // B*T tokens
#define DIM 1024     // model dim
#define FF  4096     // mlp dim
#define NH  8        // heads
#define DH  128      // head dim
#define NB  2        // batch
#define TT  2048     // seq len

// ---------------- scratch (device globals; no allocation allowed) ----------
__device__ float  g_xn  [BT * DIM];
__device__ float  g_q   [BT * DIM];
__device__ float  g_k   [BT * DIM];
__device__ float  g_v   [BT * DIM];
__device__ float  g_beta[BT * NH];
__device__ float  g_alph[BT * NH];
__device__ float  g_x1  [BT * DIM];
__device__ float  g_xn2 [BT * DIM];
__device__ float  g_hg  [BT * FF];
// half copies (GEMM operands); weights stored TRANSPOSED [N][K]
__device__ __half g_xn_h  [BT * DIM];
__device__ __half g_xn2_h [BT * DIM];
__device__ __half g_attn_h[BT * DIM];
__device__ __half g_hg_h  [BT * FF];
__device__ __half g_wq_h  [DIM * DIM];
__device__ __half g_wk_h  [DIM * DIM];
__device__ __half g_wv_h  [DIM * DIM];
__device__ __half g_wo_h  [DIM * DIM];
__device__ __half g_wga_h [DIM * FF];
__device__ __half g_wup_h [DIM * FF];
__device__ __half g_wdn_h [FF * DIM];

__device__ __forceinline__ float siluf(float x) { return x / (1.0f + __expf(-x)); }

// ---------------- transpose + fp32->half: in[K][N] -> out[N][K] ------------
__global__ __launch_bounds__(256) void conv_tr_kernel(const float* __restrict__ in,
                                                      __half* __restrict__ out,
                                                      int K, int N)
{
    __shared__ float s[32][33];
    int bx = blockIdx.x * 32;  // n base
    int by = blockIdx.y * 32;  // k base
    int tx = threadIdx.x, ty = threadIdx.y;
    #pragma unroll
    for (int j = 0; j < 4; ++j)
        s[ty + 8 * j][tx] = in[(size_t)(by + ty + 8 * j) * N + bx + tx];
    __syncthreads();
    #pragma unroll
    for (int j = 0; j < 4; ++j)
        out[(size_t)(bx + ty + 8 * j) * K + by + tx] = __float2half_rn(s[tx][ty + 8 * j]);
}

// ---------------- rmsnorm: fp32 out + half out -----------------------------
__global__ __launch_bounds__(256) void rmsnorm_kernel(const float* __restrict__ in,
                                                      float* __restrict__ out,
                                                      __half* __restrict__ out_h)
{
    int row = blockIdx.x;
    int i   = threadIdx.x * 4;
    const float* r = in + (size_t)row * DIM;
    float4 xv = *(const float4*)&r[i];
    float ss = xv.x*xv.x + xv.y*xv.y + xv.z*xv.z + xv.w*xv.w;

    #pragma unroll
    for (int o = 16; o > 0; o >>= 1) ss += __shfl_xor_sync(0xffffffffu, ss, o);
    __shared__ float sbuf[8];
    int w = threadIdx.x >> 5;
    if ((threadIdx.x & 31) == 0) sbuf[w] = ss;
    __syncthreads();
    float tot = sbuf[0]+sbuf[1]+sbuf[2]+sbuf[3]+sbuf[4]+sbuf[5]+sbuf[6]+sbuf[7];
    float scale = rsqrtf(tot * (1.0f / DIM) + 1e-6f);

    float4 ov;
    ov.x = xv.x*scale; ov.y = xv.y*scale; ov.z = xv.z*scale; ov.w = xv.w*scale;
    size_t off = (size_t)row * DIM + i;
    *(float4*)&out[off] = ov;
    __half2 h0 = __floats2half2_rn(ov.x, ov.y);
    __half2 h1 = __floats2half2_rn(ov.z, ov.w);
    *(__half2*)&out_h[off]     = h0;
    *(__half2*)&out_h[off + 2] = h1;
}

// ---------------- FP16 tensor-core GEMM, cp.async + ldmatrix ---------------
// C = A[M,K] @ Bt[N,K]^T, fp32 accumulate. Epilogue modes:
//   0: C = acc (+Res)            (fp32 out)
//   1: C = silu(acc)             (fp32 out; v projection)
//   2: Ch = half(silu(Gate)*acc) (half out; fused swiglu on up-proj)

#define AST_H 72                    // smem row stride in halves (144B)
#define A_STG (128 * AST_H)         // 9216 halves per stage
#define GEMM_SMEM (4 * A_STG * 2)   // 73728 bytes (2 stages A + 2 stages B)

__device__ __forceinline__ void cp16(uint32_t smem_dst, const void* gsrc) {
    asm volatile("cp.async.cg.shared.global [%0], [%1], 16;" :: "r"(smem_dst), "l"(gsrc));
}

__device__ __forceinline__ void ldm4(uint32_t& r0, uint32_t& r1, uint32_t& r2,
                                     uint32_t& r3, const __half* p) {
    uint32_t a = (uint32_t)__cvta_generic_to_shared(p);
    asm volatile("ldmatrix.sync.aligned.m8n8.x4.shared.b16 {%0,%1,%2,%3}, [%4];"
                 : "=r"(r0), "=r"(r1), "=r"(r2), "=r"(r3) : "r"(a));
}

__global__ __launch_bounds__(256, 2) void gemm_h_kernel(const __half* __restrict__ A,
                                                        const __half* __restrict__ Bt,
                                                        const float* __restrict__ Res,
                                                        const float* __restrict__ Gate,
                                                        float* __restrict__ C,
                                                        __half* __restrict__ Ch,
                                                        int M, int N, int K, int mode)
{
    extern __shared__ __align__(16) __half sm[];
    __half* As = sm;                  // [2][A_STG]
    __half* Bs = sm + 2 * A_STG;      // [2][A_STG]

    int tid  = threadIdx.x;
    int lane = tid & 31;
    int warp = tid >> 5;
    int g    = lane >> 2;     // 0..7
    int t4   = lane & 3;      // 0..3
    int wm   = warp & 1;
    int wn   = warp >> 1;
    int bm   = blockIdx.y * 128;
    int bn   = blockIdx.x * 128;

    int cRow  = tid >> 1;            // 0..127
    int cBase = (tid & 1) * 4;       // 16B-chunk base (0 or 4)

    // ldmatrix lane-address components
    int lm8   = lane & 7;
    int lmHi  = (lane >> 4);         // 0/1
    int lmMid = (lane >> 3) & 1;     // 0/1

    float acc[4][4][4];
    #pragma unroll
    for (int i = 0; i < 4; ++i)
        #pragma unroll
        for (int j = 0; j < 4; ++j)
            #pragma unroll
            for (int c = 0; c < 4; ++c) acc[i][j][c] = 0.f;

    int nIter = K >> 6;

    auto copy_stage = [&](int it, int stg) {
        int k0 = it << 6;
        #pragma unroll
        for (int i = 0; i < 4; ++i) {
            int c = cBase + i;       // 16B chunk = 8 halves
            uint32_t da = (uint32_t)__cvta_generic_to_shared(&As[stg * A_STG + cRow * AST_H + c * 8]);
            cp16(da, &A[(size_t)(bm + cRow) * K + k0 + c * 8]);
            uint32_t db = (uint32_t)__cvta_generic_to_shared(&Bs[stg * A_STG + cRow * AST_H + c * 8]);
            cp16(db, &Bt[(size_t)(bn + cRow) * K + k0 + c * 8]);
        }
        asm volatile("cp.async.commit_group;");
    };

    copy_stage(0, 0);

    for (int it = 0; it < nIter; ++it) {
        if (it + 1 < nIter) {
            copy_stage(it + 1, (it + 1) & 1);
            asm volatile("cp.async.wait_group 1;");
        } else {
            asm volatile("cp.async.wait_group 0;");
        }
        __syncthreads();

        const __half* Ac = As + (it & 1) * A_STG;
        const __half* Bc = Bs + (it & 1) * A_STG;

        #pragma unroll
        for (int kc = 0; kc < 64; kc += 16) {
            uint32_t bf[4][2];
            #pragma unroll
            for (int ntp = 0; ntp < 2; ++ntp) {
                int brow = wn * 32 + ntp * 16 + (lmHi << 3) + lm8;
                int bk   = kc + (lmMid << 3);
                ldm4(bf[2*ntp][0], bf[2*ntp][1], bf[2*ntp+1][0], bf[2*ntp+1][1],
                     &Bc[brow * AST_H + bk]);
            }
            #pragma unroll
            for (int mt = 0; mt < 4; ++mt) {
                int arow = wm * 64 + mt * 16 + (lmMid << 3) + lm8;
                int ak   = kc + (lmHi << 3);
                uint32_t a0, a1, a2, a3;
                ldm4(a0, a1, a2, a3, &Ac[arow * AST_H + ak]);
                #pragma unroll
                for (int nt = 0; nt < 4; ++nt) {
                    asm volatile(
                        "mma.sync.aligned.m16n8k16.row.col.f32.f16.f16.f32 "
                        "{%0,%1,%2,%3}, {%4,%5,%6,%7}, {%8,%9}, {%0,%1,%2,%3};"
                        : "+f"(acc[mt][nt][0]), "+f"(acc[mt][nt][1]),
                          "+f"(acc[mt][nt][2]), "+f"(acc[mt][nt][3])
                        : "r"(a0), "r"(a1), "r"(a2), "r"(a3),
                          "r"(bf[nt][0]), "r"(bf[nt][1]));
                }
            }
        }
        __syncthreads();
    }

    #pragma unroll
    for (int mt = 0; mt < 4; ++mt) {
        #pragma unroll
        for (int nt = 0; nt < 4; ++nt) {
            int row = bm + wm * 64 + mt * 16 + g;
            int col = bn + wn * 32 + nt * 8 + 2 * t4;
            size_t o0 = (size_t)row * N + col;
            size_t o1 = (size_t)(row + 8) * N + col;
            float2 u, l;
            u.x = acc[mt][nt][0]; u.y = acc[mt][nt][1];
            l.x = acc[mt][nt][2]; l.y = acc[mt][nt][3];
            if (mode == 0) {
                if (Res) {
                    float2 r0 = *(const float2*)&Res[o0];
                    float2 r1 = *(const float2*)&Res[o1];
                    u.x += r0.x; u.y += r0.y;
                    l.x += r1.x; l.y += r1.y;
                }
                *(float2*)&C[o0] = u;
                *(float2*)&C[o1] = l;
            } else if (mode == 1) {
                u.x = siluf(u.x); u.y = siluf(u.y);
                l.x = siluf(l.x); l.y = siluf(l.y);
                *(float2*)&C[o0] = u;
                *(float2*)&C[o1] = l;
            } else {   // mode 2: fused swiglu, half out
                float2 g0 = *(const float2*)&Gate[o0];
                float2 g1 = *(const float2*)&Gate[o1];
                __half2 h0 = __floats2half2_rn(siluf(g0.x) * u.x, siluf(g0.y) * u.y);
                __half2 h1 = __floats2half2_rn(siluf(g1.x) * l.x, siluf(g1.y) * l.y);
                *(__half2*)&Ch[o0] = h0;
                *(__half2*)&Ch[o1] = h1;
            }
        }
    }
}

// ---------------- beta/alpha: sigmoid(xn @ wb), sigmoid(xn @ wg) -----------
__global__ __launch_bounds__(256) void ba_kernel(const float* __restrict__ xn,
                                                 const float* __restrict__ wb,
                                                 const float* __restrict__ wg,
                                                 float* __restrict__ beta,
                                                 float* __restrict__ alph)
{
    __shared__ __align__(16) float xr[DIM];
    int tok = blockIdx.x;
    int t = threadIdx.x;
    *(float4*)&xr[t * 4] = *(const float4*)&xn[(size_t)tok * DIM + t * 4];
    __syncthreads();

    int w = t >> 5, lane = t & 31;
    float ab = 0.f, aa = 0.f;
    #pragma unroll 4
    for (int d = lane; d < DIM; d += 32) {
        float xv = xr[d];
        ab = fmaf(xv, wb[d * NH + w], ab);
        aa = fmaf(xv, wg[d * NH + w], aa);
    }
    #pragma unroll
    for (int o = 16; o > 0; o >>= 1) {
        ab += __shfl_xor_sync(0xffffffffu, ab, o);
        aa += __shfl_xor_sync(0xffffffffu, aa, o);
    }
    if (lane == 0) {
        beta[tok * NH + w] = 1.0f / (1.0f + expf(-ab));
        alph[tok * NH + w] = 1.0f / (1.0f + expf(-aa));
    }
}

// ---------------- activations: silu + per-head l2norm on q,k (v fused) -----
__global__ __launch_bounds__(128) void act_kernel(float* __restrict__ q,
                                                  float* __restrict__ k)
{
    int tok = blockIdx.x, h = blockIdx.y, t = threadIdx.x;
    size_t idx = (size_t)tok * DIM + h * DH + t;
    float qv = q[idx], kv = k[idx];
    float qs = qv / (1.0f + expf(-qv));
    float ks = kv / (1.0f + expf(-kv));

    float a = qs * qs, b = ks * ks;
    #pragma unroll
    for (int o = 16; o > 0; o >>= 1) {
        a += __shfl_xor_sync(0xffffffffu, a, o);
        b += __shfl_xor_sync(0xffffffffu, b, o);
    }
    __shared__ float sq[4], sk[4];
    int w = t >> 5;
    if ((t & 31) == 0) { sq[w] = a; sk[w] = b; }
    __syncthreads();
    float qsum = sq[0] + sq[1] + sq[2] + sq[3];
    float ksum = sk[0] + sk[1] + sk[2] + sk[3];

    q[idx] = qs * rsqrtf(qsum + 1e-6f);
    k[idx] = ks * rsqrtf(ksum + 1e-6f);
}

// ---------------- gated delta-rule scan, 8-way k-split, 256 thr ------------
// 64 blocks = (bh 0..15) x (column-group 0..3; 32 columns each).
// 256 threads = 8 warps -> 2 warps per SMSP (doubles FMA issue rate and
// hides shfl latency with the co-resident warp's independent work).
// Thread (warp w, lane l): column colL = w*4 + (l&3), segment seg = l>>2
// (16 k-rows). Reduction: shfl xor 4/8/16. Threads <128 stage k, >=128
// stage q. 4-deep staging: one __syncthreads per TWO timesteps.
__global__ __launch_bounds__(256) void scan_kernel(const float* __restrict__ q,
                                                   const float* __restrict__ k,
                                                   const float* __restrict__ v,
                                                   const float* __restrict__ beta,
                                                   const float* __restrict__ alph,
                                                   const float* __restrict__ state_in,
                                                   __half* __restrict__ attn_h,
                                                   float* __restrict__ state_out)
{
    int blk = blockIdx.x;
    int bh  = blk >> 2;
    int grp = blk & 3;
    int b = bh >> 3, h = bh & 7;
    int tid = threadIdx.x;
    int w = tid >> 5, lane = tid & 31;
    int colL  = w * 4 + (lane & 3);   // 0..31
    int seg   = lane >> 2;            // 0..7
    int vcol  = grp * 32 + colL;      // global state column
    int rbase = seg * 16;             // this thread's k-row range

    float S[16];
    const float* st = state_in + (size_t)bh * DH * DH;
    #pragma unroll
    for (int i = 0; i < 16; ++i) S[i] = st[(rbase + i) * DH + vcol];

    __shared__ __align__(16) float sk[4][DH];
    __shared__ __align__(16) float sq[4][DH];

    int ld = tid & 127;                       // dim index staged by this thread
    const float* kq = (tid < 128) ? k : q;    // low half stages k, high half q
    float* skq0 = (tid < 128) ? &sk[0][0] : &sq[0][0];

    size_t base0 = (size_t)(b * TT) * DIM + h * DH;
    float kq0 = kq[base0 + ld];
    float kq1 = kq[base0 + DIM + ld];
    float v0c = v[base0 + vcol];
    float v1c = v[base0 + DIM + vcol];
    float b0c = beta[(b * TT) * NH + h],     a0c = alph[(b * TT) * NH + h];
    float b1c = beta[(b * TT + 1) * NH + h], a1c = alph[(b * TT + 1) * NH + h];

    for (int t = 0; t < TT; t += 2) {
        int tok = b * TT + t;
        size_t base = (size_t)tok * DIM + h * DH;
        int u0 = t & 3, u1 = u0 + 1;
        skq0[u0 * DH + ld] = kq0;
        skq0[u1 * DH + ld] = kq1;
        float vv0 = v0c, bt0 = b0c, at0 = a0c;
        float vv1 = v1c, bt1 = b1c, at1 = a1c;
        __syncthreads();

        if (t + 2 < TT) {   // prefetch t+2, t+3 (overlaps compute)
            size_t nb = base + 2 * (size_t)DIM;
            kq0 = kq[nb + ld];
            kq1 = kq[nb + DIM + ld];
            v0c = v[nb + vcol];
            v1c = v[nb + DIM + vcol];
            b0c = beta[(tok + 2) * NH + h];  a0c = alph[(tok + 2) * NH + h];
            b1c = beta[(tok + 3) * NH + h];  a1c = alph[(tok + 3) * NH + h];
        }

        #pragma unroll
        for (int half_ = 0; half_ < 2; ++half_) {
            int ub = half_ ? u1 : u0;
            float vv = half_ ? vv1 : vv0;
            float bt = half_ ? bt1 : bt0;
            float at = half_ ? at1 : at0;
            size_t obase = base + half_ * (size_t)DIM;

            float p0 = 0.f, p1 = 0.f, p2 = 0.f, p3 = 0.f;
            #pragma unroll
            for (int i = 0; i < 16; i += 4) {
                float4 k4 = *(const float4*)&sk[ub][rbase + i];
                p0 = fmaf(k4.x, S[i + 0], p0);
                p1 = fmaf(k4.y, S[i + 1], p1);
                p2 = fmaf(k4.z, S[i + 2], p2);
                p3 = fmaf(k4.w, S[i + 3], p3);
            }
            float pred = (p0 + p1) + (p2 + p3);
            pred += __shfl_xor_sync(0xffffffffu, pred, 4);
            pred += __shfl_xor_sync(0xffffffffu, pred, 8);
            pred += __shfl_xor_sync(0xffffffffu, pred, 16);
            float dv = bt * (vv - at * pred);

            float o0 = 0.f, o1 = 0.f, o2 = 0.f, o3 = 0.f;
            #pragma unroll
            for (int i = 0; i < 16; i += 4) {
                float4 k4 = *(const float4*)&sk[ub][rbase + i];
                float4 q4 = *(const float4*)&sq[ub][rbase + i];
                float s0 = fmaf(k4.x, dv, at * S[i + 0]); S[i + 0] = s0; o0 = fmaf(q4.x, s0, o0);
                float s1 = fmaf(k4.y, dv, at * S[i + 1]); S[i + 1] = s1; o1 = fmaf(q4.y, s1, o1);
                float s2 = fmaf(k4.z, dv, at * S[i + 2]); S[i + 2] = s2; o2 = fmaf(q4.z, s2, o2);
                float s3 = fmaf(k4.w, dv, at * S[i + 3]); S[i + 3] = s3; o3 = fmaf(q4.w, s3, o3);
            }
            float o = (o0 + o1) + (o2 + o3);
            o += __shfl_xor_sync(0xffffffffu, o, 4);
            o += __shfl_xor_sync(0xffffffffu, o, 8);
            o += __shfl_xor_sync(0xffffffffu, o, 16);
            if (seg == 0) attn_h[obase + vcol] = __float2half_rn(o);
        }
    }

    float* so = state_out + (size_t)bh * DH * DH;
    #pragma unroll
    for (int i = 0; i < 16; ++i) so[(rbase + i) * DH + vcol] = S[i];
}

// ---------------- launch --------------------------------------------------
extern "C" void kernel_launch(void* const* d_in, const int* in_sizes, int n_in,
                              void* d_out, int out_size)
{
    const float* x     = (const float*)d_in[0];
    const float* state = (const float*)d_in[1];
    const float* wq    = (const float*)d_in[2];
    const float* wk    = (const float*)d_in[3];
    const float* wv    = (const float*)d_in[4];
    const float* wb    = (const float*)d_in[5];
    const float* wg    = (const float*)d_in[6];
    const float* wo    = (const float*)d_in[7];
    const float* wgate = (const float*)d_in[8];
    const float* wup   = (const float*)d_in[9];
    const float* wdown = (const float*)d_in[10];
    float* out = (float*)d_out;

    float *xn, *q, *k, *v, *beta, *alph, *x1, *xn2, *hg;
    __half *xn_h, *xn2_h, *attn_h, *hg_h;
    __half *wq_h, *wk_h, *wv_h, *wo_h, *wga_h, *wup_h, *wdn_h;
    cudaGetSymbolAddress((void**)&xn,    g_xn);
    cudaGetSymbolAddress((void**)&q,     g_q);
    cudaGetSymbolAddress((void**)&k,     g_k);
    cudaGetSymbolAddress((void**)&v,     g_v);
    cudaGetSymbolAddress((void**)&beta,  g_beta);
    cudaGetSymbolAddress((void**)&alph,  g_alph);
    cudaGetSymbolAddress((void**)&x1,    g_x1);
    cudaGetSymbolAddress((void**)&xn2,   g_xn2);
    cudaGetSymbolAddress((void**)&hg,    g_hg);
    cudaGetSymbolAddress((void**)&xn_h,  g_xn_h);
    cudaGetSymbolAddress((void**)&xn2_h, g_xn2_h);
    cudaGetSymbolAddress((void**)&attn_h,g_attn_h);
    cudaGetSymbolAddress((void**)&hg_h,  g_hg_h);
    cudaGetSymbolAddress((void**)&wq_h,  g_wq_h);
    cudaGetSymbolAddress((void**)&wk_h,  g_wk_h);
    cudaGetSymbolAddress((void**)&wv_h,  g_wv_h);
    cudaGetSymbolAddress((void**)&wo_h,  g_wo_h);
    cudaGetSymbolAddress((void**)&wga_h, g_wga_h);
    cudaGetSymbolAddress((void**)&wup_h, g_wup_h);
    cudaGetSymbolAddress((void**)&wdn_h, g_wdn_h);

    cudaFuncSetAttribute(gemm_h_kernel,
                         cudaFuncAttributeMaxDynamicSharedMemorySize, GEMM_SMEM);

    dim3 tb(32, 8);
    dim3 gD(DIM / 128, BT / 128);   // N=1024 GEMMs: 8 x 32
    dim3 gF(FF / 128,  BT / 128);   // N=4096 GEMMs: 32 x 32

    // Launch order arranged so ncu's "-s 5 -c 1" (6th launch) profiles gemm_k.
    conv_tr_kernel<<<dim3(DIM/32, DIM/32), tb>>>(wq, wq_h, DIM, DIM);          // 0
    conv_tr_kernel<<<dim3(DIM/32, DIM/32), tb>>>(wk, wk_h, DIM, DIM);          // 1
    conv_tr_kernel<<<dim3(DIM/32, DIM/32), tb>>>(wv, wv_h, DIM, DIM);          // 2
    rmsnorm_kernel<<<BT, 256>>>(x, xn, xn_h);                                  // 3
    gemm_h_kernel<<<gD, 256, GEMM_SMEM>>>(xn_h, wq_h, nullptr, nullptr,
                                          q, nullptr, BT, DIM, DIM, 0);        // 4
    gemm_h_kernel<<<gD, 256, GEMM_SMEM>>>(xn_h, wk_h, nullptr, nullptr,
                                          k, nullptr, BT, DIM, DIM, 0);        // 5 <- profiled
    gemm_h_kernel<<<gD, 256, GEMM_SMEM>>>(xn_h, wv_h, nullptr, nullptr,
                                          v, nullptr, BT, DIM, DIM, 1);        // 6 (silu fused)
    ba_kernel<<<BT, 256>>>(xn, wb, wg, beta, alph);                            // 7
    act_kernel<<<dim3(BT, NH), 128>>>(q, k);                                   // 8
    conv_tr_kernel<<<dim3(DIM/32, DIM/32), tb>>>(wo, wo_h, DIM, DIM);          // 9
    scan_kernel<<<NB * NH * 4, 256>>>(q, k, v, beta, alph, state,
                                      attn_h, out + (size_t)BT * DIM);         // 10
    gemm_h_kernel<<<gD, 256, GEMM_SMEM>>>(attn_h, wo_h, x, nullptr,
                                          x1, nullptr, BT, DIM, DIM, 0);       // 11
    rmsnorm_kernel<<<BT, 256>>>(x1, xn2, xn2_h);                               // 12
    conv_tr_kernel<<<dim3(FF/32, DIM/32), tb>>>(wgate, wga_h, DIM, FF);        // 13
    conv_tr_kernel<<<dim3(FF/32, DIM/32), tb>>>(wup,   wup_h, DIM, FF);        // 14
    gemm_h_kernel<<<gF, 256, GEMM_SMEM>>>(xn2_h, wga_h, nullptr, nullptr,
                                          hg, nullptr, BT, FF, DIM, 0);        // 15
    gemm_h_kernel<<<gF, 256, GEMM_SMEM>>>(xn2_h, wup_h, nullptr, hg,
                                          nullptr, hg_h, BT, FF, DIM, 2);      // 16 (swiglu fused)
    conv_tr_kernel<<<dim3(DIM/32, FF/32), tb>>>(wdown, wdn_h, FF, DIM);        // 17
    gemm_h_kernel<<<gD, 256, GEMM_SMEM>>>(hg_h, wdn_h, x1, nullptr,
                                          out, nullptr, BT, DIM, FF, 0);       // 18
}

// round 10
// speedup vs baseline: 1.0629x; 1.0629x over previous
#include <cuda_runtime.h>
#include <cuda_fp16.h>
#include <math.h>
#include <stdint.h>

// Problem dims (fixed by the dataset)
#define BT  4096     // B*T tokens
#define DIM 1024     // model dim
#define FF  4096     // mlp dim
#define NH  8        // heads
#define DH  128      // head dim
#define NB  2        // batch
#define TT  2048     // seq len

// ---------------- scratch (device globals; no allocation allowed) ----------
__device__ float  g_xn  [BT * DIM];
__device__ float  g_q   [BT * DIM];
__device__ float  g_k   [BT * DIM];
__device__ float  g_v   [BT * DIM];
__device__ float  g_beta[BT * NH];
__device__ float  g_alph[BT * NH];
__device__ float  g_x1  [BT * DIM];
__device__ float  g_xn2 [BT * DIM];
__device__ float  g_hg  [BT * FF];
// half copies (GEMM operands); weights stored TRANSPOSED [N][K]
__device__ __half g_xn_h  [BT * DIM];
__device__ __half g_xn2_h [BT * DIM];
__device__ __half g_attn_h[BT * DIM];
__device__ __half g_hg_h  [BT * FF];
__device__ __half g_wq_h  [DIM * DIM];
__device__ __half g_wk_h  [DIM * DIM];
__device__ __half g_wv_h  [DIM * DIM];
__device__ __half g_wo_h  [DIM * DIM];
__device__ __half g_wga_h [DIM * FF];
__device__ __half g_wup_h [DIM * FF];
__device__ __half g_wdn_h [FF * DIM];

__device__ __forceinline__ float siluf(float x) { return x / (1.0f + __expf(-x)); }

// ---------------- transpose + fp32->half: in[K][N] -> out[N][K] ------------
__global__ __launch_bounds__(256) void conv_tr_kernel(const float* __restrict__ in,
                                                      __half* __restrict__ out,
                                                      int K, int N)
{
    __shared__ float s[32][33];
    int bx = blockIdx.x * 32;  // n base
    int by = blockIdx.y * 32;  // k base
    int tx = threadIdx.x, ty = threadIdx.y;
    #pragma unroll
    for (int j = 0; j < 4; ++j)
        s[ty + 8 * j][tx] = in[(size_t)(by + ty + 8 * j) * N + bx + tx];
    __syncthreads();
    #pragma unroll
    for (int j = 0; j < 4; ++j)
        out[(size_t)(bx + ty + 8 * j) * K + by + tx] = __float2half_rn(s[tx][ty + 8 * j]);
}

// ---------------- rmsnorm: fp32 out + half out -----------------------------
__global__ __launch_bounds__(256) void rmsnorm_kernel(const float* __restrict__ in,
                                                      float* __restrict__ out,
                                                      __half* __restrict__ out_h)
{
    int row = blockIdx.x;
    int i   = threadIdx.x * 4;
    const float* r = in + (size_t)row * DIM;
    float4 xv = *(const float4*)&r[i];
    float ss = xv.x*xv.x + xv.y*xv.y + xv.z*xv.z + xv.w*xv.w;

    #pragma unroll
    for (int o = 16; o > 0; o >>= 1) ss += __shfl_xor_sync(0xffffffffu, ss, o);
    __shared__ float sbuf[8];
    int w = threadIdx.x >> 5;
    if ((threadIdx.x & 31) == 0) sbuf[w] = ss;
    __syncthreads();
    float tot = sbuf[0]+sbuf[1]+sbuf[2]+sbuf[3]+sbuf[4]+sbuf[5]+sbuf[6]+sbuf[7];
    float scale = rsqrtf(tot * (1.0f / DIM) + 1e-6f);

    float4 ov;
    ov.x = xv.x*scale; ov.y = xv.y*scale; ov.z = xv.z*scale; ov.w = xv.w*scale;
    size_t off = (size_t)row * DIM + i;
    *(float4*)&out[off] = ov;
    __half2 h0 = __floats2half2_rn(ov.x, ov.y);
    __half2 h1 = __floats2half2_rn(ov.z, ov.w);
    *(__half2*)&out_h[off]     = h0;
    *(__half2*)&out_h[off + 2] = h1;
}

// ---------------- FP16 tensor-core GEMM, cp.async + ldmatrix ---------------
// C = A[M,K] @ Bt[N,K]^T, fp32 accumulate. Epilogue modes:
//   0: C = acc (+Res)            (fp32 out)
//   1: C = silu(acc)             (fp32 out; v projection)
//   2: Ch = half(silu(Gate)*acc) (half out; fused swiglu on up-proj)

#define AST_H 72                    // smem row stride in halves (144B)
#define A_STG (128 * AST_H)         // 9216 halves per stage
#define GEMM_SMEM (4 * A_STG * 2)   // 73728 bytes (2 stages A + 2 stages B)

__device__ __forceinline__ void cp16(uint32_t smem_dst, const void* gsrc) {
    asm volatile("cp.async.cg.shared.global [%0], [%1], 16;" :: "r"(smem_dst), "l"(gsrc));
}

__device__ __forceinline__ void ldm4(uint32_t& r0, uint32_t& r1, uint32_t& r2,
                                     uint32_t& r3, const __half* p) {
    uint32_t a = (uint32_t)__cvta_generic_to_shared(p);
    asm volatile("ldmatrix.sync.aligned.m8n8.x4.shared.b16 {%0,%1,%2,%3}, [%4];"
                 : "=r"(r0), "=r"(r1), "=r"(r2), "=r"(r3) : "r"(a));
}

__global__ __launch_bounds__(256, 2) void gemm_h_kernel(const __half* __restrict__ A,
                                                        const __half* __restrict__ Bt,
                                                        const float* __restrict__ Res,
                                                        const float* __restrict__ Gate,
                                                        float* __restrict__ C,
                                                        __half* __restrict__ Ch,
                                                        int M, int N, int K, int mode)
{
    extern __shared__ __align__(16) __half sm[];
    __half* As = sm;                  // [2][A_STG]
    __half* Bs = sm + 2 * A_STG;      // [2][A_STG]

    int tid  = threadIdx.x;
    int lane = tid & 31;
    int warp = tid >> 5;
    int g    = lane >> 2;     // 0..7
    int t4   = lane & 3;      // 0..3
    int wm   = warp & 1;
    int wn   = warp >> 1;
    int bm   = blockIdx.y * 128;
    int bn   = blockIdx.x * 128;

    int cRow  = tid >> 1;            // 0..127
    int cBase = (tid & 1) * 4;       // 16B-chunk base (0 or 4)

    // ldmatrix lane-address components
    int lm8   = lane & 7;
    int lmHi  = (lane >> 4);         // 0/1
    int lmMid = (lane >> 3) & 1;     // 0/1

    float acc[4][4][4];
    #pragma unroll
    for (int i = 0; i < 4; ++i)
        #pragma unroll
        for (int j = 0; j < 4; ++j)
            #pragma unroll
            for (int c = 0; c < 4; ++c) acc[i][j][c] = 0.f;

    int nIter = K >> 6;

    auto copy_stage = [&](int it, int stg) {
        int k0 = it << 6;
        #pragma unroll
        for (int i = 0; i < 4; ++i) {
            int c = cBase + i;       // 16B chunk = 8 halves
            uint32_t da = (uint32_t)__cvta_generic_to_shared(&As[stg * A_STG + cRow * AST_H + c * 8]);
            cp16(da, &A[(size_t)(bm + cRow) * K + k0 + c * 8]);
            uint32_t db = (uint32_t)__cvta_generic_to_shared(&Bs[stg * A_STG + cRow * AST_H + c * 8]);
            cp16(db, &Bt[(size_t)(bn + cRow) * K + k0 + c * 8]);
        }
        asm volatile("cp.async.commit_group;");
    };

    copy_stage(0, 0);

    for (int it = 0; it < nIter; ++it) {
        if (it + 1 < nIter) {
            copy_stage(it + 1, (it + 1) & 1);
            asm volatile("cp.async.wait_group 1;");
        } else {
            asm volatile("cp.async.wait_group 0;");
        }
        __syncthreads();

        const __half* Ac = As + (it & 1) * A_STG;
        const __half* Bc = Bs + (it & 1) * A_STG;

        #pragma unroll
        for (int kc = 0; kc < 64; kc += 16) {
            uint32_t bf[4][2];
            #pragma unroll
            for (int ntp = 0; ntp < 2; ++ntp) {
                int brow = wn * 32 + ntp * 16 + (lmHi << 3) + lm8;
                int bk   = kc + (lmMid << 3);
                ldm4(bf[2*ntp][0], bf[2*ntp][1], bf[2*ntp+1][0], bf[2*ntp+1][1],
                     &Bc[brow * AST_H + bk]);
            }
            #pragma unroll
            for (int mt = 0; mt < 4; ++mt) {
                int arow = wm * 64 + mt * 16 + (lmMid << 3) + lm8;
                int ak   = kc + (lmHi << 3);
                uint32_t a0, a1, a2, a3;
                ldm4(a0, a1, a2, a3, &Ac[arow * AST_H + ak]);
                #pragma unroll
                for (int nt = 0; nt < 4; ++nt) {
                    asm volatile(
                        "mma.sync.aligned.m16n8k16.row.col.f32.f16.f16.f32 "
                        "{%0,%1,%2,%3}, {%4,%5,%6,%7}, {%8,%9}, {%0,%1,%2,%3};"
                        : "+f"(acc[mt][nt][0]), "+f"(acc[mt][nt][1]),
                          "+f"(acc[mt][nt][2]), "+f"(acc[mt][nt][3])
                        : "r"(a0), "r"(a1), "r"(a2), "r"(a3),
                          "r"(bf[nt][0]), "r"(bf[nt][1]));
                }
            }
        }
        __syncthreads();
    }

    #pragma unroll
    for (int mt = 0; mt < 4; ++mt) {
        #pragma unroll
        for (int nt = 0; nt < 4; ++nt) {
            int row = bm + wm * 64 + mt * 16 + g;
            int col = bn + wn * 32 + nt * 8 + 2 * t4;
            size_t o0 = (size_t)row * N + col;
            size_t o1 = (size_t)(row + 8) * N + col;
            float2 u, l;
            u.x = acc[mt][nt][0]; u.y = acc[mt][nt][1];
            l.x = acc[mt][nt][2]; l.y = acc[mt][nt][3];
            if (mode == 0) {
                if (Res) {
                    float2 r0 = *(const float2*)&Res[o0];
                    float2 r1 = *(const float2*)&Res[o1];
                    u.x += r0.x; u.y += r0.y;
                    l.x += r1.x; l.y += r1.y;
                }
                *(float2*)&C[o0] = u;
                *(float2*)&C[o1] = l;
            } else if (mode == 1) {
                u.x = siluf(u.x); u.y = siluf(u.y);
                l.x = siluf(l.x); l.y = siluf(l.y);
                *(float2*)&C[o0] = u;
                *(float2*)&C[o1] = l;
            } else {   // mode 2: fused swiglu, half out
                float2 g0 = *(const float2*)&Gate[o0];
                float2 g1 = *(const float2*)&Gate[o1];
                __half2 h0 = __floats2half2_rn(siluf(g0.x) * u.x, siluf(g0.y) * u.y);
                __half2 h1 = __floats2half2_rn(siluf(g1.x) * l.x, siluf(g1.y) * l.y);
                *(__half2*)&Ch[o0] = h0;
                *(__half2*)&Ch[o1] = h1;
            }
        }
    }
}

// ---------------- beta/alpha: sigmoid(xn @ wb), sigmoid(xn @ wg) -----------
__global__ __launch_bounds__(256) void ba_kernel(const float* __restrict__ xn,
                                                 const float* __restrict__ wb,
                                                 const float* __restrict__ wg,
                                                 float* __restrict__ beta,
                                                 float* __restrict__ alph)
{
    __shared__ __align__(16) float xr[DIM];
    int tok = blockIdx.x;
    int t = threadIdx.x;
    *(float4*)&xr[t * 4] = *(const float4*)&xn[(size_t)tok * DIM + t * 4];
    __syncthreads();

    int w = t >> 5, lane = t & 31;
    float ab = 0.f, aa = 0.f;
    #pragma unroll 4
    for (int d = lane; d < DIM; d += 32) {
        float xv = xr[d];
        ab = fmaf(xv, wb[d * NH + w], ab);
        aa = fmaf(xv, wg[d * NH + w], aa);
    }
    #pragma unroll
    for (int o = 16; o > 0; o >>= 1) {
        ab += __shfl_xor_sync(0xffffffffu, ab, o);
        aa += __shfl_xor_sync(0xffffffffu, aa, o);
    }
    if (lane == 0) {
        beta[tok * NH + w] = 1.0f / (1.0f + expf(-ab));
        alph[tok * NH + w] = 1.0f / (1.0f + expf(-aa));
    }
}

// ---------------- activations: silu + per-head l2norm on q,k (v fused) -----
__global__ __launch_bounds__(128) void act_kernel(float* __restrict__ q,
                                                  float* __restrict__ k)
{
    int tok = blockIdx.x, h = blockIdx.y, t = threadIdx.x;
    size_t idx = (size_t)tok * DIM + h * DH + t;
    float qv = q[idx], kv = k[idx];
    float qs = qv / (1.0f + expf(-qv));
    float ks = kv / (1.0f + expf(-kv));

    float a = qs * qs, b = ks * ks;
    #pragma unroll
    for (int o = 16; o > 0; o >>= 1) {
        a += __shfl_xor_sync(0xffffffffu, a, o);
        b += __shfl_xor_sync(0xffffffffu, b, o);
    }
    __shared__ float sq[4], sk[4];
    int w = t >> 5;
    if ((t & 31) == 0) { sq[w] = a; sk[w] = b; }
    __syncthreads();
    float qsum = sq[0] + sq[1] + sq[2] + sq[3];
    float ksum = sk[0] + sk[1] + sk[2] + sk[3];

    q[idx] = qs * rsqrtf(qsum + 1e-6f);
    k[idx] = ks * rsqrtf(ksum + 1e-6f);
}

// ---------------- gated delta-rule scan, 8-way k-split (R7 version) --------
// 128 blocks = (bh 0..15) x (column-group 0..7; 16 columns each).
// Thread (warp w, lane l): column colL = w*4 + (l&3), k-segment seg = l>>2
// (16 rows). Dot-product reduction via shfl xor 4/8/16. 4-deep staging
// buffers: one __syncthreads per TWO timesteps (writers use bufs
// (t+2,t+3)&3, readers (t,t+1)&3 — disjoint mod 4).
__global__ __launch_bounds__(128) void scan_kernel(const float* __restrict__ q,
                                                   const float* __restrict__ k,
                                                   const float* __restrict__ v,
                                                   const float* __restrict__ beta,
                                                   const float* __restrict__ alph,
                                                   const float* __restrict__ state_in,
                                                   __half* __restrict__ attn_h,
                                                   float* __restrict__ state_out)
{
    int blk = blockIdx.x;
    int bh  = blk >> 3;
    int grp = blk & 7;
    int b = bh >> 3, h = bh & 7;
    int tid = threadIdx.x;
    int w = tid >> 5, lane = tid & 31;
    int colL  = w * 4 + (lane & 3);   // 0..15
    int seg   = lane >> 2;            // 0..7
    int vcol  = grp * 16 + colL;      // global state column
    int rbase = seg * 16;             // this thread's k-row range

    float S[16];
    const float* st = state_in + (size_t)bh * DH * DH;
    #pragma unroll
    for (int i = 0; i < 16; ++i) S[i] = st[(rbase + i) * DH + vcol];

    __shared__ __align__(16) float sk[4][DH];
    __shared__ __align__(16) float sq[4][DH];

    size_t base0 = (size_t)(b * TT) * DIM + h * DH;
    // prefetch t=0 and t=1
    float k0c = k[base0 + tid],        q0c = q[base0 + tid],        v0c = v[base0 + vcol];
    float k1c = k[base0 + DIM + tid],  q1c = q[base0 + DIM + tid],  v1c = v[base0 + DIM + vcol];
    float b0c = beta[(b * TT) * NH + h],     a0c = alph[(b * TT) * NH + h];
    float b1c = beta[(b * TT + 1) * NH + h], a1c = alph[(b * TT + 1) * NH + h];

    for (int t = 0; t < TT; t += 2) {
        int tok = b * TT + t;
        size_t base = (size_t)tok * DIM + h * DH;
        int u0 = t & 3, u1 = u0 + 1;
        sk[u0][tid] = k0c;  sq[u0][tid] = q0c;
        sk[u1][tid] = k1c;  sq[u1][tid] = q1c;
        float vv0 = v0c, bt0 = b0c, at0 = a0c;
        float vv1 = v1c, bt1 = b1c, at1 = a1c;
        __syncthreads();

        if (t + 2 < TT) {   // prefetch t+2, t+3 (overlaps compute)
            size_t nb = base + 2 * (size_t)DIM;
            k0c = k[nb + tid];        q0c = q[nb + tid];        v0c = v[nb + vcol];
            k1c = k[nb + DIM + tid];  q1c = q[nb + DIM + tid];  v1c = v[nb + DIM + vcol];
            b0c = beta[(tok + 2) * NH + h];  a0c = alph[(tok + 2) * NH + h];
            b1c = beta[(tok + 3) * NH + h];  a1c = alph[(tok + 3) * NH + h];
        }

        #pragma unroll
        for (int half_ = 0; half_ < 2; ++half_) {
            int ub = half_ ? u1 : u0;
            float vv = half_ ? vv1 : vv0;
            float bt = half_ ? bt1 : bt0;
            float at = half_ ? at1 : at0;
            size_t obase = base + half_ * (size_t)DIM;

            float p0 = 0.f, p1 = 0.f, p2 = 0.f, p3 = 0.f;
            #pragma unroll
            for (int i = 0; i < 16; i += 4) {
                float4 k4 = *(const float4*)&sk[ub][rbase + i];
                p0 = fmaf(k4.x, S[i + 0], p0);
                p1 = fmaf(k4.y, S[i + 1], p1);
                p2 = fmaf(k4.z, S[i + 2], p2);
                p3 = fmaf(k4.w, S[i + 3], p3);
            }
            float pred = (p0 + p1) + (p2 + p3);
            pred += __shfl_xor_sync(0xffffffffu, pred, 4);
            pred += __shfl_xor_sync(0xffffffffu, pred, 8);
            pred += __shfl_xor_sync(0xffffffffu, pred, 16);
            float dv = bt * (vv - at * pred);

            float o0 = 0.f, o1 = 0.f, o2 = 0.f, o3 = 0.f;
            #pragma unroll
            for (int i = 0; i < 16; i += 4) {
                float4 k4 = *(const float4*)&sk[ub][rbase + i];
                float4 q4 = *(const float4*)&sq[ub][rbase + i];
                float s0 = fmaf(k4.x, dv, at * S[i + 0]); S[i + 0] = s0; o0 = fmaf(q4.x, s0, o0);
                float s1 = fmaf(k4.y, dv, at * S[i + 1]); S[i + 1] = s1; o1 = fmaf(q4.y, s1, o1);
                float s2 = fmaf(k4.z, dv, at * S[i + 2]); S[i + 2] = s2; o2 = fmaf(q4.z, s2, o2);
                float s3 = fmaf(k4.w, dv, at * S[i + 3]); S[i + 3] = s3; o3 = fmaf(q4.w, s3, o3);
            }
            float o = (o0 + o1) + (o2 + o3);
            o += __shfl_xor_sync(0xffffffffu, o, 4);
            o += __shfl_xor_sync(0xffffffffu, o, 8);
            o += __shfl_xor_sync(0xffffffffu, o, 16);
            if (seg == 0) attn_h[obase + vcol] = __float2half_rn(o);
        }
    }

    float* so = state_out + (size_t)bh * DH * DH;
    #pragma unroll
    for (int i = 0; i < 16; ++i) so[(rbase + i) * DH + vcol] = S[i];
}

// ---------------- launch --------------------------------------------------
extern "C" void kernel_launch(void* const* d_in, const int* in_sizes, int n_in,
                              void* d_out, int out_size)
{
    const float* x     = (const float*)d_in[0];
    const float* state = (const float*)d_in[1];
    const float* wq    = (const float*)d_in[2];
    const float* wk    = (const float*)d_in[3];
    const float* wv    = (const float*)d_in[4];
    const float* wb    = (const float*)d_in[5];
    const float* wg    = (const float*)d_in[6];
    const float* wo    = (const float*)d_in[7];
    const float* wgate = (const float*)d_in[8];
    const float* wup   = (const float*)d_in[9];
    const float* wdown = (const float*)d_in[10];
    float* out = (float*)d_out;

    float *xn, *q, *k, *v, *beta, *alph, *x1, *xn2, *hg;
    __half *xn_h, *xn2_h, *attn_h, *hg_h;
    __half *wq_h, *wk_h, *wv_h, *wo_h, *wga_h, *wup_h, *wdn_h;
    cudaGetSymbolAddress((void**)&xn,    g_xn);
    cudaGetSymbolAddress((void**)&q,     g_q);
    cudaGetSymbolAddress((void**)&k,     g_k);
    cudaGetSymbolAddress((void**)&v,     g_v);
    cudaGetSymbolAddress((void**)&beta,  g_beta);
    cudaGetSymbolAddress((void**)&alph,  g_alph);
    cudaGetSymbolAddress((void**)&x1,    g_x1);
    cudaGetSymbolAddress((void**)&xn2,   g_xn2);
    cudaGetSymbolAddress((void**)&hg,    g_hg);
    cudaGetSymbolAddress((void**)&xn_h,  g_xn_h);
    cudaGetSymbolAddress((void**)&xn2_h, g_xn2_h);
    cudaGetSymbolAddress((void**)&attn_h,g_attn_h);
    cudaGetSymbolAddress((void**)&hg_h,  g_hg_h);
    cudaGetSymbolAddress((void**)&wq_h,  g_wq_h);
    cudaGetSymbolAddress((void**)&wk_h,  g_wk_h);
    cudaGetSymbolAddress((void**)&wv_h,  g_wv_h);
    cudaGetSymbolAddress((void**)&wo_h,  g_wo_h);
    cudaGetSymbolAddress((void**)&wga_h, g_wga_h);
    cudaGetSymbolAddress((void**)&wup_h, g_wup_h);
    cudaGetSymbolAddress((void**)&wdn_h, g_wdn_h);

    cudaFuncSetAttribute(gemm_h_kernel,
                         cudaFuncAttributeMaxDynamicSharedMemorySize, GEMM_SMEM);

    dim3 tb(32, 8);
    dim3 gD(DIM / 128, BT / 128);   // N=1024 GEMMs: 8 x 32
    dim3 gF(FF / 128,  BT / 128);   // N=4096 GEMMs: 32 x 32

    // R9's profile captured launch index 3 -> put gemm_q there.
    conv_tr_kernel<<<dim3(DIM/32, DIM/32), tb>>>(wq, wq_h, DIM, DIM);          // 0
    conv_tr_kernel<<<dim3(DIM/32, DIM/32), tb>>>(wk, wk_h, DIM, DIM);          // 1
    rmsnorm_kernel<<<BT, 256>>>(x, xn, xn_h);                                  // 2
    gemm_h_kernel<<<gD, 256, GEMM_SMEM>>>(xn_h, wq_h, nullptr, nullptr,
                                          q, nullptr, BT, DIM, DIM, 0);        // 3 <- profiled
    gemm_h_kernel<<<gD, 256, GEMM_SMEM>>>(xn_h, wk_h, nullptr, nullptr,
                                          k, nullptr, BT, DIM, DIM, 0);        // 4
    conv_tr_kernel<<<dim3(DIM/32, DIM/32), tb>>>(wv, wv_h, DIM, DIM);          // 5
    gemm_h_kernel<<<gD, 256, GEMM_SMEM>>>(xn_h, wv_h, nullptr, nullptr,
                                          v, nullptr, BT, DIM, DIM, 1);        // 6 (silu fused)
    ba_kernel<<<BT, 256>>>(xn, wb, wg, beta, alph);                            // 7
    act_kernel<<<dim3(BT, NH), 128>>>(q, k);                                   // 8
    conv_tr_kernel<<<dim3(DIM/32, DIM/32), tb>>>(wo, wo_h, DIM, DIM);          // 9
    scan_kernel<<<NB * NH * 8, 128>>>(q, k, v, beta, alph, state,
                                      attn_h, out + (size_t)BT * DIM);         // 10
    gemm_h_kernel<<<gD, 256, GEMM_SMEM>>>(attn_h, wo_h, x, nullptr,
                                          x1, nullptr, BT, DIM, DIM, 0);       // 11
    rmsnorm_kernel<<<BT, 256>>>(x1, xn2, xn2_h);                               // 12
    conv_tr_kernel<<<dim3(FF/32, DIM/32), tb>>>(wgate, wga_h, DIM, FF);        // 13
    conv_tr_kernel<<<dim3(FF/32, DIM/32), tb>>>(wup,   wup_h, DIM, FF);        // 14
    gemm_h_kernel<<<gF, 256, GEMM_SMEM>>>(xn2_h, wga_h, nullptr, nullptr,
                                          hg, nullptr, BT, FF, DIM, 0);        // 15
    gemm_h_kernel<<<gF, 256, GEMM_SMEM>>>(xn2_h, wup_h, nullptr, hg,
                                          nullptr, hg_h, BT, FF, DIM, 2);      // 16 (swiglu fused)
    conv_tr_kernel<<<dim3(DIM/32, FF/32), tb>>>(wdown, wdn_h, FF, DIM);        // 17
    gemm_h_kernel<<<gD, 256, GEMM_SMEM>>>(hg_h, wdn_h, x1, nullptr,
                                          out, nullptr, BT, DIM, FF, 0);       // 18
}

// round 11
// speedup vs baseline: 1.3278x; 1.2493x over previous
#include <cuda_runtime.h>
#include <cuda_fp16.h>
#include <math.h>
#include <stdint.h>

// Problem dims (fixed by the dataset)
#define BT  4096     // B*T tokens
#define DIM 1024     // model dim
#define FF  4096     // mlp dim
#define NH  8        // heads
#define DH  128      // head dim
#define NB  2        // batch
#define TT  2048     // seq len

// ---------------- scratch (device globals; no allocation allowed) ----------
__device__ float  g_xn  [BT * DIM];
__device__ float  g_q   [BT * DIM];
__device__ float  g_k   [BT * DIM];
__device__ float  g_v   [BT * DIM];
__device__ float  g_beta[BT * NH];
__device__ float  g_alph[BT * NH];
__device__ float  g_x1  [BT * DIM];
__device__ float  g_xn2 [BT * DIM];
__device__ float  g_hg  [BT * FF];
// half GEMM operands in TILE-PACKED, PRE-SWIZZLED layout:
//   [row/128][col/64][128][64] halves, with SW128 xor (chunk c^(r&7)) applied
__device__ __half g_xn_h  [BT * DIM];
__device__ __half g_xn2_h [BT * DIM];
__device__ __half g_attn_h[BT * DIM];
__device__ __half g_hg_h  [BT * FF];
__device__ __half g_wq_h  [DIM * DIM];
__device__ __half g_wk_h  [DIM * DIM];
__device__ __half g_wv_h  [DIM * DIM];
__device__ __half g_wo_h  [DIM * DIM];
__device__ __half g_wga_h [DIM * FF];
__device__ __half g_wup_h [DIM * FF];
__device__ __half g_wdn_h [FF * DIM];

__device__ __forceinline__ float siluf(float x) { return x / (1.0f + __expf(-x)); }

// packed+swizzled half index for logical element (row, col) of a [rows, kdim]
// matrix. Tile = 128x64; within tile the 16B chunk index is xor-swizzled.
__device__ __forceinline__ size_t packA(int row, int col, int kdim) {
    size_t tile = (size_t)(row >> 7) * (kdim >> 6) + (col >> 6);
    int r = row & 127, c = col & 63;
    return tile * 8192 + r * 64 + ((((c >> 3) ^ (r & 7)) << 3) | (c & 7));
}

// ---------------- transpose + fp32->half (packed): in[K][N] -> packed[N][K]
__global__ __launch_bounds__(256) void conv_tr_kernel(const float* __restrict__ in,
                                                      __half* __restrict__ out,
                                                      int K, int N)
{
    __shared__ float s[32][33];
    int bx = blockIdx.x * 32;  // n base
    int by = blockIdx.y * 32;  // k base
    int tx = threadIdx.x, ty = threadIdx.y;
    #pragma unroll
    for (int j = 0; j < 4; ++j)
        s[ty + 8 * j][tx] = in[(size_t)(by + ty + 8 * j) * N + bx + tx];
    __syncthreads();
    #pragma unroll
    for (int j = 0; j < 4; ++j) {
        int n = bx + ty + 8 * j;
        int k = by + tx;
        out[packA(n, k, K)] = __float2half_rn(s[tx][ty + 8 * j]);
    }
}

// ---------------- rmsnorm: fp32 out + packed half out ----------------------
__global__ __launch_bounds__(256) void rmsnorm_kernel(const float* __restrict__ in,
                                                      float* __restrict__ out,
                                                      __half* __restrict__ out_h)
{
    int row = blockIdx.x;
    int i   = threadIdx.x * 4;
    const float* r = in + (size_t)row * DIM;
    float4 xv = *(const float4*)&r[i];
    float ss = xv.x*xv.x + xv.y*xv.y + xv.z*xv.z + xv.w*xv.w;

    #pragma unroll
    for (int o = 16; o > 0; o >>= 1) ss += __shfl_xor_sync(0xffffffffu, ss, o);
    __shared__ float sbuf[8];
    int w = threadIdx.x >> 5;
    if ((threadIdx.x & 31) == 0) sbuf[w] = ss;
    __syncthreads();
    float tot = sbuf[0]+sbuf[1]+sbuf[2]+sbuf[3]+sbuf[4]+sbuf[5]+sbuf[6]+sbuf[7];
    float scale = rsqrtf(tot * (1.0f / DIM) + 1e-6f);

    float4 ov;
    ov.x = xv.x*scale; ov.y = xv.y*scale; ov.z = xv.z*scale; ov.w = xv.w*scale;
    *(float4*)&out[(size_t)row * DIM + i] = ov;
    size_t po = packA(row, i, DIM);          // i%8 in {0,4}: 4 halves in-chunk
    *(__half2*)&out_h[po]     = __floats2half2_rn(ov.x, ov.y);
    *(__half2*)&out_h[po + 2] = __floats2half2_rn(ov.z, ov.w);
}

// ---------------- FP16 tensor-core GEMM, cp.async.bulk + ldmatrix ----------
// C = A[M,K] @ Bt[N,K]^T, fp32 accumulate. A/Bt are packed+swizzled halves.
// BM=128, BN=128, BK=64; 256 threads = 8 warps 2(m)x4(n); warp tile 64x32.
// Per stage: TWO cp.async.bulk (16KB each) + mbarrier, replacing 2048 cp.async.

#define TILE_H   8192                 // halves per 128x64 tile
#define STG_H    (2 * TILE_H)         // A+B per stage
#define GEMM_SMEM (2 * STG_H * 2)     // 65536 bytes (2 stages)

__device__ __forceinline__ void ldm4(uint32_t& r0, uint32_t& r1, uint32_t& r2,
                                     uint32_t& r3, const __half* p) {
    uint32_t a = (uint32_t)__cvta_generic_to_shared(p);
    asm volatile("ldmatrix.sync.aligned.m8n8.x4.shared.b16 {%0,%1,%2,%3}, [%4];"
                 : "=r"(r0), "=r"(r1), "=r"(r2), "=r"(r3) : "r"(a));
}

__device__ __forceinline__ void mbar_wait(uint32_t mbar, uint32_t parity) {
    asm volatile(
        "{\n\t.reg .pred P;\n\t"
        "WL%=:\n\t"
        "mbarrier.try_wait.parity.acquire.cta.shared::cta.b64 P, [%0], %1, 0x989680;\n\t"
        "@P bra.uni WD%=;\n\t"
        "bra.uni WL%=;\n\t"
        "WD%=:\n\t}"
        :: "r"(mbar), "r"(parity) : "memory");
}

__global__ __launch_bounds__(256, 2) void gemm_h_kernel(const __half* __restrict__ A,
                                                        const __half* __restrict__ Bt,
                                                        const float* __restrict__ Res,
                                                        const float* __restrict__ Gate,
                                                        float* __restrict__ C,
                                                        __half* __restrict__ Ch,
                                                        int M, int N, int K, int mode)
{
    extern __shared__ __align__(16) __half sm[];   // [2][A tile | B tile]
    __shared__ __align__(8) uint64_t mbar[2];

    int tid  = threadIdx.x;
    int lane = tid & 31;
    int warp = tid >> 5;
    int g    = lane >> 2;     // 0..7
    int t4   = lane & 3;      // 0..3
    int wm   = warp & 1;
    int wn   = warp >> 1;
    int bm   = blockIdx.y * 128;
    int bn   = blockIdx.x * 128;

    // ldmatrix lane-address components
    int lm8   = lane & 7;
    int lmHi  = (lane >> 4);         // 0/1
    int lmMid = (lane >> 3) & 1;     // 0/1

    uint32_t mb[2];
    mb[0] = (uint32_t)__cvta_generic_to_shared(&mbar[0]);
    mb[1] = (uint32_t)__cvta_generic_to_shared(&mbar[1]);
    if (tid == 0) {
        asm volatile("mbarrier.init.shared.b64 [%0], 1;" :: "r"(mb[0]) : "memory");
        asm volatile("mbarrier.init.shared.b64 [%0], 1;" :: "r"(mb[1]) : "memory");
        asm volatile("fence.proxy.async.shared::cta;" ::: "memory");
    }
    __syncthreads();

    int nIter = K >> 6;
    int kt = K >> 6;   // tiles per row-of-tiles

    auto issue_stage = [&](int s) {
        int b = s & 1;
        uint32_t m = mb[b];
        asm volatile("mbarrier.arrive.expect_tx.shared.b64 _, [%0], %1;"
                     :: "r"(m), "r"(32768u) : "memory");
        const __half* ga = A  + ((size_t)blockIdx.y * kt + s) * TILE_H;
        const __half* gb = Bt + ((size_t)blockIdx.x * kt + s) * TILE_H;
        uint32_t da = (uint32_t)__cvta_generic_to_shared(sm + b * STG_H);
        uint32_t db = da + TILE_H * 2;
        asm volatile("cp.async.bulk.shared::cta.global.mbarrier::complete_tx::bytes [%0], [%1], %2, [%3];"
                     :: "r"(da), "l"(ga), "r"(16384u), "r"(m) : "memory");
        asm volatile("cp.async.bulk.shared::cta.global.mbarrier::complete_tx::bytes [%0], [%1], %2, [%3];"
                     :: "r"(db), "l"(gb), "r"(16384u), "r"(m) : "memory");
    };

    float acc[4][4][4];
    #pragma unroll
    for (int i = 0; i < 4; ++i)
        #pragma unroll
        for (int j = 0; j < 4; ++j)
            #pragma unroll
            for (int c = 0; c < 4; ++c) acc[i][j][c] = 0.f;

    if (tid == 0) issue_stage(0);

    for (int it = 0; it < nIter; ++it) {
        if (tid == 0 && it + 1 < nIter) issue_stage(it + 1);
        mbar_wait(mb[it & 1], (it >> 1) & 1);

        const __half* Ac = sm + (it & 1) * STG_H;
        const __half* Bc = Ac + TILE_H;

        #pragma unroll
        for (int kc = 0; kc < 64; kc += 16) {
            // B fragments: one x4 covers 2 n-tiles
            uint32_t bf[4][2];
            #pragma unroll
            for (int ntp = 0; ntp < 2; ++ntp) {
                int brow = wn * 32 + ntp * 16 + (lmHi << 3) + lm8;
                int bk   = kc + (lmMid << 3);
                ldm4(bf[2*ntp][0], bf[2*ntp][1], bf[2*ntp+1][0], bf[2*ntp+1][1],
                     Bc + brow * 64 + (((bk >> 3) ^ (brow & 7)) << 3));
            }
            #pragma unroll
            for (int mt = 0; mt < 4; ++mt) {
                int arow = wm * 64 + mt * 16 + (lmMid << 3) + lm8;
                int ak   = kc + (lmHi << 3);
                uint32_t a0, a1, a2, a3;
                ldm4(a0, a1, a2, a3,
                     Ac + arow * 64 + (((ak >> 3) ^ (arow & 7)) << 3));
                #pragma unroll
                for (int nt = 0; nt < 4; ++nt) {
                    asm volatile(
                        "mma.sync.aligned.m16n8k16.row.col.f32.f16.f16.f32 "
                        "{%0,%1,%2,%3}, {%4,%5,%6,%7}, {%8,%9}, {%0,%1,%2,%3};"
                        : "+f"(acc[mt][nt][0]), "+f"(acc[mt][nt][1]),
                          "+f"(acc[mt][nt][2]), "+f"(acc[mt][nt][3])
                        : "r"(a0), "r"(a1), "r"(a2), "r"(a3),
                          "r"(bf[nt][0]), "r"(bf[nt][1]));
                }
            }
        }
        __syncthreads();   // all warps done reading this stage before its reuse
    }

    #pragma unroll
    for (int mt = 0; mt < 4; ++mt) {
        #pragma unroll
        for (int nt = 0; nt < 4; ++nt) {
            int row = bm + wm * 64 + mt * 16 + g;
            int col = bn + wn * 32 + nt * 8 + 2 * t4;
            size_t o0 = (size_t)row * N + col;
            size_t o1 = (size_t)(row + 8) * N + col;
            float2 u, l;
            u.x = acc[mt][nt][0]; u.y = acc[mt][nt][1];
            l.x = acc[mt][nt][2]; l.y = acc[mt][nt][3];
            if (mode == 0) {
                if (Res) {
                    float2 r0 = *(const float2*)&Res[o0];
                    float2 r1 = *(const float2*)&Res[o1];
                    u.x += r0.x; u.y += r0.y;
                    l.x += r1.x; l.y += r1.y;
                }
                *(float2*)&C[o0] = u;
                *(float2*)&C[o1] = l;
            } else if (mode == 1) {
                u.x = siluf(u.x); u.y = siluf(u.y);
                l.x = siluf(l.x); l.y = siluf(l.y);
                *(float2*)&C[o0] = u;
                *(float2*)&C[o1] = l;
            } else {   // mode 2: fused swiglu, packed half out
                float2 g0 = *(const float2*)&Gate[o0];
                float2 g1 = *(const float2*)&Gate[o1];
                *(__half2*)&Ch[packA(row,     col, N)] =
                    __floats2half2_rn(siluf(g0.x) * u.x, siluf(g0.y) * u.y);
                *(__half2*)&Ch[packA(row + 8, col, N)] =
                    __floats2half2_rn(siluf(g1.x) * l.x, siluf(g1.y) * l.y);
            }
        }
    }
}

// ---------------- beta/alpha: sigmoid(xn @ wb), sigmoid(xn @ wg) -----------
__global__ __launch_bounds__(256) void ba_kernel(const float* __restrict__ xn,
                                                 const float* __restrict__ wb,
                                                 const float* __restrict__ wg,
                                                 float* __restrict__ beta,
                                                 float* __restrict__ alph)
{
    __shared__ __align__(16) float xr[DIM];
    int tok = blockIdx.x;
    int t = threadIdx.x;
    *(float4*)&xr[t * 4] = *(const float4*)&xn[(size_t)tok * DIM + t * 4];
    __syncthreads();

    int w = t >> 5, lane = t & 31;
    float ab = 0.f, aa = 0.f;
    #pragma unroll 4
    for (int d = lane; d < DIM; d += 32) {
        float xv = xr[d];
        ab = fmaf(xv, wb[d * NH + w], ab);
        aa = fmaf(xv, wg[d * NH + w], aa);
    }
    #pragma unroll
    for (int o = 16; o > 0; o >>= 1) {
        ab += __shfl_xor_sync(0xffffffffu, ab, o);
        aa += __shfl_xor_sync(0xffffffffu, aa, o);
    }
    if (lane == 0) {
        beta[tok * NH + w] = 1.0f / (1.0f + expf(-ab));
        alph[tok * NH + w] = 1.0f / (1.0f + expf(-aa));
    }
}

// ---------------- activations: silu + per-head l2norm on q,k (v fused) -----
__global__ __launch_bounds__(128) void act_kernel(float* __restrict__ q,
                                                  float* __restrict__ k)
{
    int tok = blockIdx.x, h = blockIdx.y, t = threadIdx.x;
    size_t idx = (size_t)tok * DIM + h * DH + t;
    float qv = q[idx], kv = k[idx];
    float qs = qv / (1.0f + expf(-qv));
    float ks = kv / (1.0f + expf(-kv));

    float a = qs * qs, b = ks * ks;
    #pragma unroll
    for (int o = 16; o > 0; o >>= 1) {
        a += __shfl_xor_sync(0xffffffffu, a, o);
        b += __shfl_xor_sync(0xffffffffu, b, o);
    }
    __shared__ float sq[4], sk[4];
    int w = t >> 5;
    if ((t & 31) == 0) { sq[w] = a; sk[w] = b; }
    __syncthreads();
    float qsum = sq[0] + sq[1] + sq[2] + sq[3];
    float ksum = sk[0] + sk[1] + sk[2] + sk[3];

    q[idx] = qs * rsqrtf(qsum + 1e-6f);
    k[idx] = ks * rsqrtf(ksum + 1e-6f);
}

// ---------------- gated delta-rule scan, 8-way k-split (R7 version) --------
// 128 blocks = (bh 0..15) x (column-group 0..7; 16 columns each).
__global__ __launch_bounds__(128) void scan_kernel(const float* __restrict__ q,
                                                   const float* __restrict__ k,
                                                   const float* __restrict__ v,
                                                   const float* __restrict__ beta,
                                                   const float* __restrict__ alph,
                                                   const float* __restrict__ state_in,
                                                   __half* __restrict__ attn_h,
                                                   float* __restrict__ state_out)
{
    int blk = blockIdx.x;
    int bh  = blk >> 3;
    int grp = blk & 7;
    int b = bh >> 3, h = bh & 7;
    int tid = threadIdx.x;
    int w = tid >> 5, lane = tid & 31;
    int colL  = w * 4 + (lane & 3);   // 0..15
    int seg   = lane >> 2;            // 0..7
    int vcol  = grp * 16 + colL;      // global state column
    int rbase = seg * 16;             // this thread's k-row range

    float S[16];
    const float* st = state_in + (size_t)bh * DH * DH;
    #pragma unroll
    for (int i = 0; i < 16; ++i) S[i] = st[(rbase + i) * DH + vcol];

    __shared__ __align__(16) float sk[4][DH];
    __shared__ __align__(16) float sq[4][DH];

    size_t base0 = (size_t)(b * TT) * DIM + h * DH;
    float k0c = k[base0 + tid],        q0c = q[base0 + tid],        v0c = v[base0 + vcol];
    float k1c = k[base0 + DIM + tid],  q1c = q[base0 + DIM + tid],  v1c = v[base0 + DIM + vcol];
    float b0c = beta[(b * TT) * NH + h],     a0c = alph[(b * TT) * NH + h];
    float b1c = beta[(b * TT + 1) * NH + h], a1c = alph[(b * TT + 1) * NH + h];

    for (int t = 0; t < TT; t += 2) {
        int tok = b * TT + t;
        size_t base = (size_t)tok * DIM + h * DH;
        int u0 = t & 3, u1 = u0 + 1;
        sk[u0][tid] = k0c;  sq[u0][tid] = q0c;
        sk[u1][tid] = k1c;  sq[u1][tid] = q1c;
        float vv0 = v0c, bt0 = b0c, at0 = a0c;
        float vv1 = v1c, bt1 = b1c, at1 = a1c;
        __syncthreads();

        if (t + 2 < TT) {   // prefetch t+2, t+3 (overlaps compute)
            size_t nb = base + 2 * (size_t)DIM;
            k0c = k[nb + tid];        q0c = q[nb + tid];        v0c = v[nb + vcol];
            k1c = k[nb + DIM + tid];  q1c = q[nb + DIM + tid];  v1c = v[nb + DIM + vcol];
            b0c = beta[(tok + 2) * NH + h];  a0c = alph[(tok + 2) * NH + h];
            b1c = beta[(tok + 3) * NH + h];  a1c = alph[(tok + 3) * NH + h];
        }

        #pragma unroll
        for (int half_ = 0; half_ < 2; ++half_) {
            int ub = half_ ? u1 : u0;
            float vv = half_ ? vv1 : vv0;
            float bt = half_ ? bt1 : bt0;
            float at = half_ ? at1 : at0;

            float p0 = 0.f, p1 = 0.f, p2 = 0.f, p3 = 0.f;
            #pragma unroll
            for (int i = 0; i < 16; i += 4) {
                float4 k4 = *(const float4*)&sk[ub][rbase + i];
                p0 = fmaf(k4.x, S[i + 0], p0);
                p1 = fmaf(k4.y, S[i + 1], p1);
                p2 = fmaf(k4.z, S[i + 2], p2);
                p3 = fmaf(k4.w, S[i + 3], p3);
            }
            float pred = (p0 + p1) + (p2 + p3);
            pred += __shfl_xor_sync(0xffffffffu, pred, 4);
            pred += __shfl_xor_sync(0xffffffffu, pred, 8);
            pred += __shfl_xor_sync(0xffffffffu, pred, 16);
            float dv = bt * (vv - at * pred);

            float o0 = 0.f, o1 = 0.f, o2 = 0.f, o3 = 0.f;
            #pragma unroll
            for (int i = 0; i < 16; i += 4) {
                float4 k4 = *(const float4*)&sk[ub][rbase + i];
                float4 q4 = *(const float4*)&sq[ub][rbase + i];
                float s0 = fmaf(k4.x, dv, at * S[i + 0]); S[i + 0] = s0; o0 = fmaf(q4.x, s0, o0);
                float s1 = fmaf(k4.y, dv, at * S[i + 1]); S[i + 1] = s1; o1 = fmaf(q4.y, s1, o1);
                float s2 = fmaf(k4.z, dv, at * S[i + 2]); S[i + 2] = s2; o2 = fmaf(q4.z, s2, o2);
                float s3 = fmaf(k4.w, dv, at * S[i + 3]); S[i + 3] = s3; o3 = fmaf(q4.w, s3, o3);
            }
            float o = (o0 + o1) + (o2 + o3);
            o += __shfl_xor_sync(0xffffffffu, o, 4);
            o += __shfl_xor_sync(0xffffffffu, o, 8);
            o += __shfl_xor_sync(0xffffffffu, o, 16);
            if (seg == 0)
                attn_h[packA(tok + half_, h * DH + vcol, DIM)] = __float2half_rn(o);
        }
    }

    float* so = state_out + (size_t)bh * DH * DH;
    #pragma unroll
    for (int i = 0; i < 16; ++i) so[(rbase + i) * DH + vcol] = S[i];
}

// ---------------- launch --------------------------------------------------
extern "C" void kernel_launch(void* const* d_in, const int* in_sizes, int n_in,
                              void* d_out, int out_size)
{
    const float* x     = (const float*)d_in[0];
    const float* state = (const float*)d_in[1];
    const float* wq    = (const float*)d_in[2];
    const float* wk    = (const float*)d_in[3];
    const float* wv    = (const float*)d_in[4];
    const float* wb    = (const float*)d_in[5];
    const float* wg    = (const float*)d_in[6];
    const float* wo    = (const float*)d_in[7];
    const float* wgate = (const float*)d_in[8];
    const float* wup   = (const float*)d_in[9];
    const float* wdown = (const float*)d_in[10];
    float* out = (float*)d_out;

    float *xn, *q, *k, *v, *beta, *alph, *x1, *xn2, *hg;
    __half *xn_h, *xn2_h, *attn_h, *hg_h;
    __half *wq_h, *wk_h, *wv_h, *wo_h, *wga_h, *wup_h, *wdn_h;
    cudaGetSymbolAddress((void**)&xn,    g_xn);
    cudaGetSymbolAddress((void**)&q,     g_q);
    cudaGetSymbolAddress((void**)&k,     g_k);
    cudaGetSymbolAddress((void**)&v,     g_v);
    cudaGetSymbolAddress((void**)&beta,  g_beta);
    cudaGetSymbolAddress((void**)&alph,  g_alph);
    cudaGetSymbolAddress((void**)&x1,    g_x1);
    cudaGetSymbolAddress((void**)&xn2,   g_xn2);
    cudaGetSymbolAddress((void**)&hg,    g_hg);
    cudaGetSymbolAddress((void**)&xn_h,  g_xn_h);
    cudaGetSymbolAddress((void**)&xn2_h, g_xn2_h);
    cudaGetSymbolAddress((void**)&attn_h,g_attn_h);
    cudaGetSymbolAddress((void**)&hg_h,  g_hg_h);
    cudaGetSymbolAddress((void**)&wq_h,  g_wq_h);
    cudaGetSymbolAddress((void**)&wk_h,  g_wk_h);
    cudaGetSymbolAddress((void**)&wv_h,  g_wv_h);
    cudaGetSymbolAddress((void**)&wo_h,  g_wo_h);
    cudaGetSymbolAddress((void**)&wga_h, g_wga_h);
    cudaGetSymbolAddress((void**)&wup_h, g_wup_h);
    cudaGetSymbolAddress((void**)&wdn_h, g_wdn_h);

    cudaFuncSetAttribute(gemm_h_kernel,
                         cudaFuncAttributeMaxDynamicSharedMemorySize, GEMM_SMEM);

    dim3 tb(32, 8);
    dim3 gD(DIM / 128, BT / 128);   // N=1024 GEMMs: 8 x 32
    dim3 gF(FF / 128,  BT / 128);   // N=4096 GEMMs: 32 x 32

    conv_tr_kernel<<<dim3(DIM/32, DIM/32), tb>>>(wq, wq_h, DIM, DIM);          // 0
    conv_tr_kernel<<<dim3(DIM/32, DIM/32), tb>>>(wk, wk_h, DIM, DIM);          // 1
    rmsnorm_kernel<<<BT, 256>>>(x, xn, xn_h);                                  // 2
    gemm_h_kernel<<<gD, 256, GEMM_SMEM>>>(xn_h, wq_h, nullptr, nullptr,
                                          q, nullptr, BT, DIM, DIM, 0);        // 3 <- profiled
    gemm_h_kernel<<<gD, 256, GEMM_SMEM>>>(xn_h, wk_h, nullptr, nullptr,
                                          k, nullptr, BT, DIM, DIM, 0);        // 4
    conv_tr_kernel<<<dim3(DIM/32, DIM/32), tb>>>(wv, wv_h, DIM, DIM);          // 5
    gemm_h_kernel<<<gD, 256, GEMM_SMEM>>>(xn_h, wv_h, nullptr, nullptr,
                                          v, nullptr, BT, DIM, DIM, 1);        // 6 (silu fused)
    ba_kernel<<<BT, 256>>>(xn, wb, wg, beta, alph);                            // 7
    act_kernel<<<dim3(BT, NH), 128>>>(q, k);                                   // 8
    conv_tr_kernel<<<dim3(DIM/32, DIM/32), tb>>>(wo, wo_h, DIM, DIM);          // 9
    scan_kernel<<<NB * NH * 8, 128>>>(q, k, v, beta, alph, state,
                                      attn_h, out + (size_t)BT * DIM);         // 10
    gemm_h_kernel<<<gD, 256, GEMM_SMEM>>>(attn_h, wo_h, x, nullptr,
                                          x1, nullptr, BT, DIM, DIM, 0);       // 11
    rmsnorm_kernel<<<BT, 256>>>(x1, xn2, xn2_h);                               // 12
    conv_tr_kernel<<<dim3(FF/32, DIM/32), tb>>>(wgate, wga_h, DIM, FF);        // 13
    conv_tr_kernel<<<dim3(FF/32, DIM/32), tb>>>(wup,   wup_h, DIM, FF);        // 14
    gemm_h_kernel<<<gF, 256, GEMM_SMEM>>>(xn2_h, wga_h, nullptr, nullptr,
                                          hg, nullptr, BT, FF, DIM, 0);        // 15
    gemm_h_kernel<<<gF, 256, GEMM_SMEM>>>(xn2_h, wup_h, nullptr, hg,
                                          nullptr, hg_h, BT, FF, DIM, 2);      // 16 (swiglu fused)
    conv_tr_kernel<<<dim3(DIM/32, FF/32), tb>>>(wdown, wdn_h, FF, DIM);        // 17
    gemm_h_kernel<<<gD, 256, GEMM_SMEM>>>(hg_h, wdn_h, x1, nullptr,
                                          out, nullptr, BT, DIM, FF, 0);       // 18
}

// round 14
// speedup vs baseline: 1.3605x; 1.0246x over previous
#include <cuda_runtime.h>
#include <cuda_fp16.h>
#include <math.h>
#include <stdint.h>

// Problem dims (fixed by the dataset)
#define BT  4096     // B*T tokens
#define DIM 1024     // model dim
#define FF  4096     // mlp dim
#define NH  8        // heads
#define DH  128      // head dim
#define NB  2        // batch
#define TT  2048     // seq len

// ---------------- scratch (device globals; no allocation allowed) ----------
__device__ float  g_xn  [BT * DIM];
__device__ float  g_q   [BT * DIM];
__device__ float  g_k   [BT * DIM];
__device__ float  g_v   [BT * DIM];
__device__ float  g_beta[BT * NH];
__device__ float  g_alph[BT * NH];
__device__ float  g_x1  [BT * DIM];
__device__ float  g_xn2 [BT * DIM];
__device__ float  g_hg  [BT * FF];
// half GEMM operands in TILE-PACKED, PRE-SWIZZLED layout:
//   [row/128][col/64][128][64] halves, 16B-chunk xor (c^(r&7))
__device__ __half g_xn_h  [BT * DIM];
__device__ __half g_xn2_h [BT * DIM];
__device__ __half g_attn_h[BT * DIM];
__device__ __half g_hg_h  [BT * FF];
__device__ __half g_wq_h  [DIM * DIM];
__device__ __half g_wk_h  [DIM * DIM];
__device__ __half g_wv_h  [DIM * DIM];
__device__ __half g_wo_h  [DIM * DIM];
__device__ __half g_wga_h [DIM * FF];
__device__ __half g_wup_h [DIM * FF];
__device__ __half g_wdn_h [FF * DIM];

__device__ __forceinline__ float siluf(float x) { return x / (1.0f + __expf(-x)); }

__device__ __forceinline__ size_t packA(int row, int col, int kdim) {
    size_t tile = (size_t)(row >> 7) * (kdim >> 6) + (col >> 6);
    int r = row & 127, c = col & 63;
    return tile * 8192 + r * 64 + ((((c >> 3) ^ (r & 7)) << 3) | (c & 7));
}

// ---------------- transpose + fp32->half (packed): in[K][N] -> packed[N][K]
__global__ __launch_bounds__(256) void conv_tr_kernel(const float* __restrict__ in,
                                                      __half* __restrict__ out,
                                                      int K, int N)
{
    __shared__ float s[32][33];
    int bx = blockIdx.x * 32;
    int by = blockIdx.y * 32;
    int tx = threadIdx.x, ty = threadIdx.y;
    #pragma unroll
    for (int j = 0; j < 4; ++j)
        s[ty + 8 * j][tx] = in[(size_t)(by + ty + 8 * j) * N + bx + tx];
    __syncthreads();
    #pragma unroll
    for (int j = 0; j < 4; ++j) {
        int n = bx + ty + 8 * j;
        int k = by + tx;
        out[packA(n, k, K)] = __float2half_rn(s[tx][ty + 8 * j]);
    }
}

// ---------------- rmsnorm: fp32 out + packed half out ----------------------
__global__ __launch_bounds__(256) void rmsnorm_kernel(const float* __restrict__ in,
                                                      float* __restrict__ out,
                                                      __half* __restrict__ out_h)
{
    int row = blockIdx.x;
    int i   = threadIdx.x * 4;
    const float* r = in + (size_t)row * DIM;
    float4 xv = *(const float4*)&r[i];
    float ss = xv.x*xv.x + xv.y*xv.y + xv.z*xv.z + xv.w*xv.w;

    #pragma unroll
    for (int o = 16; o > 0; o >>= 1) ss += __shfl_xor_sync(0xffffffffu, ss, o);
    __shared__ float sbuf[8];
    int w = threadIdx.x >> 5;
    if ((threadIdx.x & 31) == 0) sbuf[w] = ss;
    __syncthreads();
    float tot = sbuf[0]+sbuf[1]+sbuf[2]+sbuf[3]+sbuf[4]+sbuf[5]+sbuf[6]+sbuf[7];
    float scale = rsqrtf(tot * (1.0f / DIM) + 1e-6f);

    float4 ov;
    ov.x = xv.x*scale; ov.y = xv.y*scale; ov.z = xv.z*scale; ov.w = xv.w*scale;
    *(float4*)&out[(size_t)row * DIM + i] = ov;
    size_t po = packA(row, i, DIM);
    *(__half2*)&out_h[po]     = __floats2half2_rn(ov.x, ov.y);
    *(__half2*)&out_h[po + 2] = __floats2half2_rn(ov.z, ov.w);
}

// ---------------- FP16 mma.sync GEMM, 3-stage cp.async.bulk + ldmatrix -----
// C = A[M,K] @ Bt[N,K]^T, fp32 accumulate. A/Bt packed+swizzled halves.
// BM=128, BN=128, BK=64; 256 threads = 8 warps 2(m)x4(n); warp tile 64x32.

#define TILE_H   8192                 // halves per 128x64 tile
#define STG_H    (2 * TILE_H)         // A+B per stage
#define NSTG 3
#define GEMM_SMEM (NSTG * STG_H * 2)  // 98304 bytes

__device__ __forceinline__ void ldm4(uint32_t& r0, uint32_t& r1, uint32_t& r2,
                                     uint32_t& r3, const __half* p) {
    uint32_t a = (uint32_t)__cvta_generic_to_shared(p);
    asm volatile("ldmatrix.sync.aligned.m8n8.x4.shared.b16 {%0,%1,%2,%3}, [%4];"
                 : "=r"(r0), "=r"(r1), "=r"(r2), "=r"(r3) : "r"(a));
}

__device__ __forceinline__ void mbar_wait(uint32_t mbar, uint32_t parity) {
    asm volatile(
        "{\n\t.reg .pred P;\n\t"
        "WL%=:\n\t"
        "mbarrier.try_wait.parity.acquire.cta.shared::cta.b64 P, [%0], %1, 0x989680;\n\t"
        "@P bra.uni WD%=;\n\t"
        "bra.uni WL%=;\n\t"
        "WD%=:\n\t}"
        :: "r"(mbar), "r"(parity) : "memory");
}

__global__ __launch_bounds__(256, 2) void gemm_h_kernel(const __half* __restrict__ A,
                                                        const __half* __restrict__ Bt,
                                                        const float* __restrict__ Res,
                                                        const float* __restrict__ Gate,
                                                        float* __restrict__ C,
                                                        __half* __restrict__ Ch,
                                                        int M, int N, int K, int mode)
{
    extern __shared__ __align__(16) __half sm[];   // [NSTG][A tile | B tile]
    __shared__ __align__(8) uint64_t mbar[NSTG];

    int tid  = threadIdx.x;
    int lane = tid & 31;
    int warp = tid >> 5;
    int g    = lane >> 2;
    int t4   = lane & 3;
    int wm   = warp & 1;
    int wn   = warp >> 1;
    int bm   = blockIdx.y * 128;
    int bn   = blockIdx.x * 128;

    int lm8   = lane & 7;
    int lmHi  = (lane >> 4);
    int lmMid = (lane >> 3) & 1;

    uint32_t mb[NSTG];
    #pragma unroll
    for (int s = 0; s < NSTG; ++s)
        mb[s] = (uint32_t)__cvta_generic_to_shared(&mbar[s]);
    if (tid == 0) {
        #pragma unroll
        for (int s = 0; s < NSTG; ++s)
            asm volatile("mbarrier.init.shared.b64 [%0], 1;" :: "r"(mb[s]) : "memory");
        asm volatile("fence.proxy.async.shared::cta;" ::: "memory");
    }
    __syncthreads();

    int nIter = K >> 6;
    int kt = K >> 6;

    auto issue_stage = [&](int s) {
        int b = s % NSTG;
        uint32_t m = mb[b];
        asm volatile("mbarrier.arrive.expect_tx.shared.b64 _, [%0], %1;"
                     :: "r"(m), "r"(32768u) : "memory");
        const __half* ga = A  + ((size_t)blockIdx.y * kt + s) * TILE_H;
        const __half* gb = Bt + ((size_t)blockIdx.x * kt + s) * TILE_H;
        uint32_t da = (uint32_t)__cvta_generic_to_shared(sm + b * STG_H);
        asm volatile("cp.async.bulk.shared::cta.global.mbarrier::complete_tx::bytes [%0], [%1], %2, [%3];"
                     :: "r"(da), "l"(ga), "r"(16384u), "r"(m) : "memory");
        asm volatile("cp.async.bulk.shared::cta.global.mbarrier::complete_tx::bytes [%0], [%1], %2, [%3];"
                     :: "r"(da + TILE_H * 2), "l"(gb), "r"(16384u), "r"(m) : "memory");
    };

    float acc[4][4][4];
    #pragma unroll
    for (int i = 0; i < 4; ++i)
        #pragma unroll
        for (int j = 0; j < 4; ++j)
            #pragma unroll
            for (int c = 0; c < 4; ++c) acc[i][j][c] = 0.f;

    if (tid == 0) {
        issue_stage(0);
        if (nIter > 1) issue_stage(1);
    }

    for (int it = 0; it < nIter; ++it) {
        if (tid == 0 && it + 2 < nIter) issue_stage(it + 2);
        mbar_wait(mb[it % NSTG], (it / NSTG) & 1);

        const __half* Ac = sm + (it % NSTG) * STG_H;
        const __half* Bc = Ac + TILE_H;

        #pragma unroll
        for (int kc = 0; kc < 64; kc += 16) {
            uint32_t bf[4][2];
            #pragma unroll
            for (int ntp = 0; ntp < 2; ++ntp) {
                int brow = wn * 32 + ntp * 16 + (lmHi << 3) + lm8;
                int bk   = kc + (lmMid << 3);
                ldm4(bf[2*ntp][0], bf[2*ntp][1], bf[2*ntp+1][0], bf[2*ntp+1][1],
                     Bc + brow * 64 + (((bk >> 3) ^ (brow & 7)) << 3));
            }
            #pragma unroll
            for (int mt = 0; mt < 4; ++mt) {
                int arow = wm * 64 + mt * 16 + (lmMid << 3) + lm8;
                int ak   = kc + (lmHi << 3);
                uint32_t a0, a1, a2, a3;
                ldm4(a0, a1, a2, a3,
                     Ac + arow * 64 + (((ak >> 3) ^ (arow & 7)) << 3));
                #pragma unroll
                for (int nt = 0; nt < 4; ++nt) {
                    asm volatile(
                        "mma.sync.aligned.m16n8k16.row.col.f32.f16.f16.f32 "
                        "{%0,%1,%2,%3}, {%4,%5,%6,%7}, {%8,%9}, {%0,%1,%2,%3};"
                        : "+f"(acc[mt][nt][0]), "+f"(acc[mt][nt][1]),
                          "+f"(acc[mt][nt][2]), "+f"(acc[mt][nt][3])
                        : "r"(a0), "r"(a1), "r"(a2), "r"(a3),
                          "r"(bf[nt][0]), "r"(bf[nt][1]));
                }
            }
        }
        __syncthreads();   // all warps done with this stage before its reuse
    }

    #pragma unroll
    for (int mt = 0; mt < 4; ++mt) {
        #pragma unroll
        for (int nt = 0; nt < 4; ++nt) {
            int row = bm + wm * 64 + mt * 16 + g;
            int col = bn + wn * 32 + nt * 8 + 2 * t4;
            size_t o0 = (size_t)row * N + col;
            size_t o1 = (size_t)(row + 8) * N + col;
            float2 u, l;
            u.x = acc[mt][nt][0]; u.y = acc[mt][nt][1];
            l.x = acc[mt][nt][2]; l.y = acc[mt][nt][3];
            if (mode == 0) {
                if (Res) {
                    float2 r0 = *(const float2*)&Res[o0];
                    float2 r1 = *(const float2*)&Res[o1];
                    u.x += r0.x; u.y += r0.y;
                    l.x += r1.x; l.y += r1.y;
                }
                *(float2*)&C[o0] = u;
                *(float2*)&C[o1] = l;
            } else if (mode == 1) {
                u.x = siluf(u.x); u.y = siluf(u.y);
                l.x = siluf(l.x); l.y = siluf(l.y);
                *(float2*)&C[o0] = u;
                *(float2*)&C[o1] = l;
            } else {   // mode 2: fused swiglu, packed half out
                float2 g0 = *(const float2*)&Gate[o0];
                float2 g1 = *(const float2*)&Gate[o1];
                *(__half2*)&Ch[packA(row,     col, N)] =
                    __floats2half2_rn(siluf(g0.x) * u.x, siluf(g0.y) * u.y);
                *(__half2*)&Ch[packA(row + 8, col, N)] =
                    __floats2half2_rn(siluf(g1.x) * l.x, siluf(g1.y) * l.y);
            }
        }
    }
}

// ---------------- beta/alpha: sigmoid(xn @ wb), sigmoid(xn @ wg) -----------
__global__ __launch_bounds__(256) void ba_kernel(const float* __restrict__ xn,
                                                 const float* __restrict__ wb,
                                                 const float* __restrict__ wg,
                                                 float* __restrict__ beta,
                                                 float* __restrict__ alph)
{
    __shared__ __align__(16) float xr[DIM];
    int tok = blockIdx.x;
    int t = threadIdx.x;
    *(float4*)&xr[t * 4] = *(const float4*)&xn[(size_t)tok * DIM + t * 4];
    __syncthreads();

    int w = t >> 5, lane = t & 31;
    float ab = 0.f, aa = 0.f;
    #pragma unroll 4
    for (int d = lane; d < DIM; d += 32) {
        float xv = xr[d];
        ab = fmaf(xv, wb[d * NH + w], ab);
        aa = fmaf(xv, wg[d * NH + w], aa);
    }
    #pragma unroll
    for (int o = 16; o > 0; o >>= 1) {
        ab += __shfl_xor_sync(0xffffffffu, ab, o);
        aa += __shfl_xor_sync(0xffffffffu, aa, o);
    }
    if (lane == 0) {
        beta[tok * NH + w] = 1.0f / (1.0f + expf(-ab));
        alph[tok * NH + w] = 1.0f / (1.0f + expf(-aa));
    }
}

// ---------------- activations: silu + per-head l2norm on q,k ---------------
__global__ __launch_bounds__(128) void act_kernel(float* __restrict__ q,
                                                  float* __restrict__ k)
{
    int tok = blockIdx.x, h = blockIdx.y, t = threadIdx.x;
    size_t idx = (size_t)tok * DIM + h * DH + t;
    float qv = q[idx], kv = k[idx];
    float qs = qv / (1.0f + expf(-qv));
    float ks = kv / (1.0f + expf(-kv));

    float a = qs * qs, b = ks * ks;
    #pragma unroll
    for (int o = 16; o > 0; o >>= 1) {
        a += __shfl_xor_sync(0xffffffffu, a, o);
        b += __shfl_xor_sync(0xffffffffu, b, o);
    }
    __shared__ float sq[4], sk[4];
    int w = t >> 5;
    if ((t & 31) == 0) { sq[w] = a; sk[w] = b; }
    __syncthreads();
    float qsum = sq[0] + sq[1] + sq[2] + sq[3];
    float ksum = sk[0] + sk[1] + sk[2] + sk[3];

    q[idx] = qs * rsqrtf(qsum + 1e-6f);
    k[idx] = ks * rsqrtf(ksum + 1e-6f);
}

// ---------------- gated delta-rule scan, 8-way k-split (R7 version) --------
__global__ __launch_bounds__(128) void scan_kernel(const float* __restrict__ q,
                                                   const float* __restrict__ k,
                                                   const float* __restrict__ v,
                                                   const float* __restrict__ beta,
                                                   const float* __restrict__ alph,
                                                   const float* __restrict__ state_in,
                                                   __half* __restrict__ attn_h,
                                                   float* __restrict__ state_out)
{
    int blk = blockIdx.x;
    int bh  = blk >> 3;
    int grp = blk & 7;
    int b = bh >> 3, h = bh & 7;
    int tid = threadIdx.x;
    int w = tid >> 5, lane = tid & 31;
    int colL  = w * 4 + (lane & 3);
    int seg   = lane >> 2;
    int vcol  = grp * 16 + colL;
    int rbase = seg * 16;

    float S[16];
    const float* st = state_in + (size_t)bh * DH * DH;
    #pragma unroll
    for (int i = 0; i < 16; ++i) S[i] = st[(rbase + i) * DH + vcol];

    __shared__ __align__(16) float sk[4][DH];
    __shared__ __align__(16) float sq[4][DH];

    size_t base0 = (size_t)(b * TT) * DIM + h * DH;
    float k0c = k[base0 + tid],        q0c = q[base0 + tid],        v0c = v[base0 + vcol];
    float k1c = k[base0 + DIM + tid],  q1c = q[base0 + DIM + tid],  v1c = v[base0 + DIM + vcol];
    float b0c = beta[(b * TT) * NH + h],     a0c = alph[(b * TT) * NH + h];
    float b1c = beta[(b * TT + 1) * NH + h], a1c = alph[(b * TT + 1) * NH + h];

    for (int t = 0; t < TT; t += 2) {
        int tok = b * TT + t;
        size_t base = (size_t)tok * DIM + h * DH;
        int u0 = t & 3, u1 = u0 + 1;
        sk[u0][tid] = k0c;  sq[u0][tid] = q0c;
        sk[u1][tid] = k1c;  sq[u1][tid] = q1c;
        float vv0 = v0c, bt0 = b0c, at0 = a0c;
        float vv1 = v1c, bt1 = b1c, at1 = a1c;
        __syncthreads();

        if (t + 2 < TT) {
            size_t nb = base + 2 * (size_t)DIM;
            k0c = k[nb + tid];        q0c = q[nb + tid];        v0c = v[nb + vcol];
            k1c = k[nb + DIM + tid];  q1c = q[nb + DIM + tid];  v1c = v[nb + DIM + vcol];
            b0c = beta[(tok + 2) * NH + h];  a0c = alph[(tok + 2) * NH + h];
            b1c = beta[(tok + 3) * NH + h];  a1c = alph[(tok + 3) * NH + h];
        }

        #pragma unroll
        for (int half_ = 0; half_ < 2; ++half_) {
            int ub = half_ ? u1 : u0;
            float vv = half_ ? vv1 : vv0;
            float bt = half_ ? bt1 : bt0;
            float at = half_ ? at1 : at0;

            float p0 = 0.f, p1 = 0.f, p2 = 0.f, p3 = 0.f;
            #pragma unroll
            for (int i = 0; i < 16; i += 4) {
                float4 k4 = *(const float4*)&sk[ub][rbase + i];
                p0 = fmaf(k4.x, S[i + 0], p0);
                p1 = fmaf(k4.y, S[i + 1], p1);
                p2 = fmaf(k4.z, S[i + 2], p2);
                p3 = fmaf(k4.w, S[i + 3], p3);
            }
            float pred = (p0 + p1) + (p2 + p3);
            pred += __shfl_xor_sync(0xffffffffu, pred, 4);
            pred += __shfl_xor_sync(0xffffffffu, pred, 8);
            pred += __shfl_xor_sync(0xffffffffu, pred, 16);
            float dv = bt * (vv - at * pred);

            float o0 = 0.f, o1 = 0.f, o2 = 0.f, o3 = 0.f;
            #pragma unroll
            for (int i = 0; i < 16; i += 4) {
                float4 k4 = *(const float4*)&sk[ub][rbase + i];
                float4 q4 = *(const float4*)&sq[ub][rbase + i];
                float s0 = fmaf(k4.x, dv, at * S[i + 0]); S[i + 0] = s0; o0 = fmaf(q4.x, s0, o0);
                float s1 = fmaf(k4.y, dv, at * S[i + 1]); S[i + 1] = s1; o1 = fmaf(q4.y, s1, o1);
                float s2 = fmaf(k4.z, dv, at * S[i + 2]); S[i + 2] = s2; o2 = fmaf(q4.z, s2, o2);
                float s3 = fmaf(k4.w, dv, at * S[i + 3]); S[i + 3] = s3; o3 = fmaf(q4.w, s3, o3);
            }
            float o = (o0 + o1) + (o2 + o3);
            o += __shfl_xor_sync(0xffffffffu, o, 4);
            o += __shfl_xor_sync(0xffffffffu, o, 8);
            o += __shfl_xor_sync(0xffffffffu, o, 16);
            if (seg == 0)
                attn_h[packA(tok + half_, h * DH + vcol, DIM)] = __float2half_rn(o);
        }
    }

    float* so = state_out + (size_t)bh * DH * DH;
    #pragma unroll
    for (int i = 0; i < 16; ++i) so[(rbase + i) * DH + vcol] = S[i];
}

// ---------------- launch --------------------------------------------------
extern "C" void kernel_launch(void* const* d_in, const int* in_sizes, int n_in,
                              void* d_out, int out_size)
{
    const float* x     = (const float*)d_in[0];
    const float* state = (const float*)d_in[1];
    const float* wq    = (const float*)d_in[2];
    const float* wk    = (const float*)d_in[3];
    const float* wv    = (const float*)d_in[4];
    const float* wb    = (const float*)d_in[5];
    const float* wg    = (const float*)d_in[6];
    const float* wo    = (const float*)d_in[7];
    const float* wgate = (const float*)d_in[8];
    const float* wup   = (const float*)d_in[9];
    const float* wdown = (const float*)d_in[10];
    float* out = (float*)d_out;

    float *xn, *q, *k, *v, *beta, *alph, *x1, *xn2, *hg;
    __half *xn_h, *xn2_h, *attn_h, *hg_h;
    __half *wq_h, *wk_h, *wv_h, *wo_h, *wga_h, *wup_h, *wdn_h;
    cudaGetSymbolAddress((void**)&xn,    g_xn);
    cudaGetSymbolAddress((void**)&q,     g_q);
    cudaGetSymbolAddress((void**)&k,     g_k);
    cudaGetSymbolAddress((void**)&v,     g_v);
    cudaGetSymbolAddress((void**)&beta,  g_beta);
    cudaGetSymbolAddress((void**)&alph,  g_alph);
    cudaGetSymbolAddress((void**)&x1,    g_x1);
    cudaGetSymbolAddress((void**)&xn2,   g_xn2);
    cudaGetSymbolAddress((void**)&hg,    g_hg);
    cudaGetSymbolAddress((void**)&xn_h,  g_xn_h);
    cudaGetSymbolAddress((void**)&xn2_h, g_xn2_h);
    cudaGetSymbolAddress((void**)&attn_h,g_attn_h);
    cudaGetSymbolAddress((void**)&hg_h,  g_hg_h);
    cudaGetSymbolAddress((void**)&wq_h,  g_wq_h);
    cudaGetSymbolAddress((void**)&wk_h,  g_wk_h);
    cudaGetSymbolAddress((void**)&wv_h,  g_wv_h);
    cudaGetSymbolAddress((void**)&wo_h,  g_wo_h);
    cudaGetSymbolAddress((void**)&wga_h, g_wga_h);
    cudaGetSymbolAddress((void**)&wup_h, g_wup_h);
    cudaGetSymbolAddress((void**)&wdn_h, g_wdn_h);

    cudaFuncSetAttribute(gemm_h_kernel,
                         cudaFuncAttributeMaxDynamicSharedMemorySize, GEMM_SMEM);

    dim3 tb(32, 8);
    dim3 gD(DIM / 128, BT / 128);   // 8 x 32
    dim3 gF(FF / 128,  BT / 128);   // 32 x 32

    conv_tr_kernel<<<dim3(DIM/32, DIM/32), tb>>>(wq, wq_h, DIM, DIM);          // 0
    conv_tr_kernel<<<dim3(DIM/32, DIM/32), tb>>>(wk, wk_h, DIM, DIM);          // 1
    rmsnorm_kernel<<<BT, 256>>>(x, xn, xn_h);                                  // 2
    gemm_h_kernel<<<gD, 256, GEMM_SMEM>>>(xn_h, wq_h, nullptr, nullptr,
                                          q, nullptr, BT, DIM, DIM, 0);        // 3 <- profiled
    gemm_h_kernel<<<gD, 256, GEMM_SMEM>>>(xn_h, wk_h, nullptr, nullptr,
                                          k, nullptr, BT, DIM, DIM, 0);        // 4
    conv_tr_kernel<<<dim3(DIM/32, DIM/32), tb>>>(wv, wv_h, DIM, DIM);          // 5
    gemm_h_kernel<<<gD, 256, GEMM_SMEM>>>(xn_h, wv_h, nullptr, nullptr,
                                          v, nullptr, BT, DIM, DIM, 1);        // 6 (silu fused)
    ba_kernel<<<BT, 256>>>(xn, wb, wg, beta, alph);                            // 7
    act_kernel<<<dim3(BT, NH), 128>>>(q, k);                                   // 8
    conv_tr_kernel<<<dim3(DIM/32, DIM/32), tb>>>(wo, wo_h, DIM, DIM);          // 9
    scan_kernel<<<NB * NH * 8, 128>>>(q, k, v, beta, alph, state,
                                      attn_h, out + (size_t)BT * DIM);         // 10
    gemm_h_kernel<<<gD, 256, GEMM_SMEM>>>(attn_h, wo_h, x, nullptr,
                                          x1, nullptr, BT, DIM, DIM, 0);       // 11
    rmsnorm_kernel<<<BT, 256>>>(x1, xn2, xn2_h);                               // 12
    conv_tr_kernel<<<dim3(FF/32, DIM/32), tb>>>(wgate, wga_h, DIM, FF);        // 13
    conv_tr_kernel<<<dim3(FF/32, DIM/32), tb>>>(wup,   wup_h, DIM, FF);        // 14
    gemm_h_kernel<<<gF, 256, GEMM_SMEM>>>(xn2_h, wga_h, nullptr, nullptr,
                                          hg, nullptr, BT, FF, DIM, 0);        // 15
    gemm_h_kernel<<<gF, 256, GEMM_SMEM>>>(xn2_h, wup_h, nullptr, hg,
                                          nullptr, hg_h, BT, FF, DIM, 2);      // 16 (swiglu fused)
    conv_tr_kernel<<<dim3(DIM/32, FF/32), tb>>>(wdown, wdn_h, FF, DIM);        // 17
    gemm_h_kernel<<<gD, 256, GEMM_SMEM>>>(hg_h, wdn_h, x1, nullptr,
                                          out, nullptr, BT, DIM, FF, 0);       // 18
}